// round 5
// baseline (speedup 1.0000x reference)
#include <cuda_runtime.h>
#include <math.h>
#include <stdint.h>

#define BB 8
#define TT 2048
#define CC 512
#define NNODE 1024

// ============================ scratch (static) ============================
#define AL __align__(128)
__device__ AL float2 g_x2[BB * TT * CC];     // interleaved (hi,lo) 67MB
__device__ AL float2 g_xT2[BB * CC * TT];    // 67MB
__device__ AL float2 g_Wq2[NNODE * TT];
__device__ AL float2 g_Wk2[CC * CC];
__device__ AL float2 g_Wv2[CC * CC];
__device__ AL float2 g_Wo2[CC * CC];
__device__ AL float2 g_k2[BB * TT * CC];     // 67MB
__device__ AL float2 g_q2[BB * NNODE * CC];  // 33MB
__device__ AL float2 g_op2[BB * NNODE * CC]; // 67MB
__device__ AL float g_v[BB * TT * CC];       // 33MB
__device__ AL float g_op[BB * NNODE * CC];   // 33MB
__device__ AL unsigned long long g_colmax[BB * TT];
__device__ AL unsigned int g_Mkey[BB * NNODE];
__device__ AL float g_Z[BB * NNODE];

// ============================ helpers ============================
__device__ __forceinline__ unsigned int fkey(float f) {
    unsigned int u = __float_as_uint(f);
    return (u & 0x80000000u) ? ~u : (u | 0x80000000u);
}
__device__ __forceinline__ float funkey(unsigned int u) {
    unsigned int v = (u & 0x80000000u) ? (u & 0x7fffffffu) : ~u;
    return __uint_as_float(v);
}
__device__ __forceinline__ float tf32_round(float x) {
    unsigned int r;
    asm("cvt.rna.tf32.f32 %0, %1;" : "=r"(r) : "f"(x));
    return __uint_as_float(r);
}
__device__ __forceinline__ uint32_t smem_u32(const void* p) {
    uint32_t a;
    asm("{ .reg .u64 t; cvta.to.shared.u64 t, %1; cvt.u32.u64 %0, t; }" : "=r"(a) : "l"(p));
    return a;
}
__device__ __forceinline__ void cp16(uint32_t dst, const void* src) {
    asm volatile("cp.async.cg.shared.global [%0], [%1], 16;" :: "r"(dst), "l"(src) : "memory");
}
__device__ __forceinline__ void cp_commit() {
    asm volatile("cp.async.commit_group;" ::: "memory");
}
template <int N> __device__ __forceinline__ void cp_wait() {
    asm volatile("cp.async.wait_group %0;" :: "n"(N) : "memory");
}
__device__ __forceinline__ void mma8(float& d0, float& d1, float& d2, float& d3,
                                     unsigned a0, unsigned a1, unsigned a2, unsigned a3,
                                     unsigned b0, unsigned b1) {
    asm volatile(
        "mma.sync.aligned.m16n8k8.row.col.f32.tf32.tf32.f32 "
        "{%0,%1,%2,%3},{%4,%5,%6,%7},{%8,%9},{%0,%1,%2,%3};"
        : "+f"(d0), "+f"(d1), "+f"(d2), "+f"(d3)
        : "r"(a0), "r"(a1), "r"(a2), "r"(a3), "r"(b0), "r"(b1));
}

// ============================ mma.sync tf32 split GEMM (interleaved hi/lo) ============================
// C[m,n] = sum_k A[m,k]*B[n,k], A/B stored as float2(hi,lo).
// NTERM=3: ah*bh + ah*bl + al*bh.  NTERM=2: ah*bh + al*bh (B-lo dropped).
// Block 128x128, BK=16, 8 warps 2(m) x 4(n), warp tile 64x32.
// EPI: 0 plain->Cp, 1 plain+colbias->Cp, 2 hilo->C2, 3 hilo+rowbias->C2, 4 argmax->colmax
static const int SROW2 = 20;                        // float2 per smem row (160B, conflict-free LDS.64)
static const int TILE_BYTES = 128 * SROW2 * 8;      // 20480
static const int STAGE_BYTES = 2 * TILE_BYTES;      // 40960
static const int RED_OFF = 2 * STAGE_BYTES;         // 81920
static const int SMEM_SZ = RED_OFF + 1024;          // 82944

template <int EPI, int NTERM>
__global__ __launch_bounds__(256, 2) void gemm_mma(
    const float2* __restrict__ A2, const float2* __restrict__ B2,
    const float* __restrict__ bias,
    float* __restrict__ Cp, float2* __restrict__ C2,
    int Nd, int K,
    long sAz, long sBz, long sCz,
    float scale, unsigned long long* colmax, long sMz)
{
    extern __shared__ __align__(16) char smem[];
    const uint32_t sb = smem_u32(smem);
    const int tid = threadIdx.x;
    const int lane = tid & 31;
    const int wid = tid >> 5;
    const int wm = wid >> 2;            // 0..1
    const int wn = wid & 3;             // 0..3
    const int grp = lane >> 2;          // 0..7
    const int qd = lane & 3;            // 0..3
    const int z = blockIdx.z;
    const long m0 = (long)blockIdx.y * 128;
    const long n0 = (long)blockIdx.x * 128;

    // ---- loader: 2048 x 16B chunks per stage (2 tiles x 128 rows x 8 chunks) ----
    const float2* pT[2] = { A2 + z * sAz + m0 * K, B2 + z * sBz + n0 * K };
    const float2* src[8];
    uint32_t dst[8];
#pragma unroll
    for (int i = 0; i < 8; i++) {
        int w = i * 256 + tid;          // 0..2047
        int tile = w >> 10;
        int row = (w >> 3) & 127;
        int ch = w & 7;
        src[i] = pT[tile] + (long)row * K + ch * 2;
        dst[i] = tile * TILE_BYTES + row * (SROW2 * 8) + ch * 16;
    }

    const int nKB = K >> 4;             // BK = 16

#pragma unroll
    for (int i = 0; i < 8; i++) cp16(sb + dst[i], src[i]);
    cp_commit();

    float acc[4][4][4];
#pragma unroll
    for (int mf = 0; mf < 4; mf++)
#pragma unroll
        for (int nf = 0; nf < 4; nf++)
#pragma unroll
            for (int r = 0; r < 4; r++) acc[mf][nf][r] = 0.f;

    for (int kb = 0; kb < nKB; kb++) {
        if (kb + 1 < nKB) {
            uint32_t so = ((kb + 1) & 1) * STAGE_BYTES;
            const long ko = (long)(kb + 1) * 16;
#pragma unroll
            for (int i = 0; i < 8; i++) cp16(sb + so + dst[i], src[i] + ko);
            cp_commit();
            cp_wait<1>();
        } else {
            cp_wait<0>();
        }
        __syncthreads();

        const float2* As2 = (const float2*)(smem + (kb & 1) * STAGE_BYTES);
        const float2* Bs2 = (const float2*)(smem + (kb & 1) * STAGE_BYTES + TILE_BYTES);

#pragma unroll
        for (int ks = 0; ks < 2; ks++) {
            const int k0 = ks * 8;
            float2 b0[4], b1[4];
#pragma unroll
            for (int nf = 0; nf < 4; nf++) {
                int r = wn * 32 + nf * 8 + grp;
                b0[nf] = Bs2[r * SROW2 + k0 + qd];
                b1[nf] = Bs2[r * SROW2 + k0 + qd + 4];
            }
#pragma unroll
            for (int mf = 0; mf < 4; mf++) {
                int r = wm * 64 + mf * 16 + grp;
                float2 fa0 = As2[r * SROW2 + k0 + qd];
                float2 fa1 = As2[(r + 8) * SROW2 + k0 + qd];
                float2 fa2 = As2[r * SROW2 + k0 + qd + 4];
                float2 fa3 = As2[(r + 8) * SROW2 + k0 + qd + 4];
                unsigned ah0 = __float_as_uint(fa0.x), al0 = __float_as_uint(fa0.y);
                unsigned ah1 = __float_as_uint(fa1.x), al1 = __float_as_uint(fa1.y);
                unsigned ah2 = __float_as_uint(fa2.x), al2 = __float_as_uint(fa2.y);
                unsigned ah3 = __float_as_uint(fa3.x), al3 = __float_as_uint(fa3.y);
#pragma unroll
                for (int nf = 0; nf < 4; nf++) {
                    float* d = acc[mf][nf];
                    unsigned bh0 = __float_as_uint(b0[nf].x), bh1 = __float_as_uint(b1[nf].x);
                    mma8(d[0], d[1], d[2], d[3], ah0, ah1, ah2, ah3, bh0, bh1);
                    if constexpr (NTERM == 3) {
                        unsigned bl0 = __float_as_uint(b0[nf].y), bl1 = __float_as_uint(b1[nf].y);
                        mma8(d[0], d[1], d[2], d[3], ah0, ah1, ah2, ah3, bl0, bl1);
                    }
                    mma8(d[0], d[1], d[2], d[3], al0, al1, al2, al3, bh0, bh1);
                }
            }
        }
        __syncthreads();
    }

    // ---------------- epilogue ----------------
    if constexpr (EPI == 4) {
        unsigned long long* red = (unsigned long long*)(smem + RED_OFF);
        if (tid < 128) red[tid] = 0ull;
        __syncthreads();
#pragma unroll
        for (int mf = 0; mf < 4; mf++) {
#pragma unroll
            for (int half = 0; half < 2; half++) {
                int lrow = wm * 64 + mf * 16 + grp + half * 8;
                float bv = -INFINITY; int bc = 0;
#pragma unroll
                for (int nf = 0; nf < 4; nf++) {
#pragma unroll
                    for (int c = 0; c < 2; c++) {
                        float vv = acc[mf][nf][half * 2 + c];
                        int col = (int)n0 + wn * 32 + nf * 8 + qd * 2 + c;
                        if (vv > bv) { bv = vv; bc = col; }
                    }
                }
                unsigned long long pack =
                    ((unsigned long long)fkey(bv * scale) << 32) | (unsigned int)bc;
                unsigned long long o;
                o = __shfl_xor_sync(0xffffffffu, pack, 1); if (o > pack) pack = o;
                o = __shfl_xor_sync(0xffffffffu, pack, 2); if (o > pack) pack = o;
                if (qd == 0) atomicMax(&red[lrow], pack);
            }
        }
        __syncthreads();
        if (tid < 128)
            atomicMax(&colmax[z * sMz + m0 + tid], red[tid]);
    } else {
#pragma unroll
        for (int mf = 0; mf < 4; mf++) {
#pragma unroll
            for (int half = 0; half < 2; half++) {
                long row = m0 + wm * 64 + mf * 16 + grp + half * 8;
                float rb = 0.f;
                if constexpr (EPI == 3) rb = bias[row];
                long base = z * sCz + row * (long)Nd + n0 + wn * 32 + qd * 2;
#pragma unroll
                for (int nf = 0; nf < 4; nf++) {
                    float v0 = acc[mf][nf][half * 2 + 0];
                    float v1 = acc[mf][nf][half * 2 + 1];
                    long off = base + nf * 8;
                    if constexpr (EPI == 0 || EPI == 1) {
                        if constexpr (EPI == 1) {
                            v0 += bias[n0 + wn * 32 + nf * 8 + qd * 2 + 0];
                            v1 += bias[n0 + wn * 32 + nf * 8 + qd * 2 + 1];
                        }
                        *reinterpret_cast<float2*>(&Cp[off]) = make_float2(v0, v1);
                    } else {
                        v0 += rb; v1 += rb;
                        float h0 = tf32_round(v0), l0 = v0 - h0;
                        float h1 = tf32_round(v1), l1 = v1 - h1;
                        float4 o4 = make_float4(h0, l0, h1, l1);
                        *reinterpret_cast<float4*>(&C2[off]) = o4;
                    }
                }
            }
        }
    }
}

// ============================ small kernels ============================
__global__ void init_kernel() {
    int i = blockIdx.x * blockDim.x + threadIdx.x;
    int stride = gridDim.x * blockDim.x;
    for (int j = i; j < BB * TT; j += stride) g_colmax[j] = 0ull;
    for (int j = i; j < BB * NNODE; j += stride) { g_Mkey[j] = 0u; g_Z[j] = 0.f; }
    for (int j = i; j < BB * NNODE * CC; j += stride) g_op[j] = 0.f;
}

__global__ void split2i(const float* __restrict__ in, float2* __restrict__ out, long n) {
    long i = (long)blockIdx.x * blockDim.x + threadIdx.x;
    long stride = (long)gridDim.x * blockDim.x;
    for (long j = i; j < n; j += stride) {
        float v = in[j];
        float h = tf32_round(v);
        out[j] = make_float2(h, v - h);
    }
}

__global__ void transpose_split(const float* __restrict__ x) {
    __shared__ float tile[32][33];
    int z = blockIdx.z;
    int t0 = blockIdx.x * 32, c0 = blockIdx.y * 32;
    int tx = threadIdx.x, ty = threadIdx.y;
#pragma unroll
    for (int i = 0; i < 32; i += 8)
        tile[ty + i][tx] = x[((long)z * TT + t0 + ty + i) * CC + c0 + tx];
    __syncthreads();
#pragma unroll
    for (int i = 0; i < 32; i += 8) {
        float v = tile[tx][ty + i];
        long o = ((long)z * CC + c0 + ty + i) * TT + t0 + tx;
        float h = tf32_round(v);
        g_xT2[o] = make_float2(h, v - h);
    }
}

// split all 4 weight matrices in one launch (keeps kernel count low for profiling)
__global__ void splitW_all(const float* __restrict__ Wq, const float* __restrict__ Wk,
                           const float* __restrict__ Wv, const float* __restrict__ Wo) {
    const long nq = (long)NNODE * TT, nw = (long)CC * CC;
    long i = (long)blockIdx.x * blockDim.x + threadIdx.x;
    long stride = (long)gridDim.x * blockDim.x;
    long total = nq + 3 * nw;
    for (long j = i; j < total; j += stride) {
        float v; float2* dst; long o;
        if (j < nq) { v = Wq[j]; dst = g_Wq2; o = j; }
        else if (j < nq + nw) { o = j - nq; v = Wk[o]; dst = g_Wk2; }
        else if (j < nq + 2 * nw) { o = j - nq - nw; v = Wv[o]; dst = g_Wv2; }
        else { o = j - nq - 2 * nw; v = Wo[o]; dst = g_Wo2; }
        float h = tf32_round(v);
        dst[o] = make_float2(h, v - h);
    }
}

__global__ void node_max_kernel() {
    int i = blockIdx.x * blockDim.x + threadIdx.x;
    if (i >= BB * TT) return;
    int b = i / TT;
    unsigned long long p = g_colmax[i];
    unsigned int n = (unsigned int)(p & 0xffffffffu);
    atomicMax(&g_Mkey[b * NNODE + n], (unsigned int)(p >> 32));
}

__global__ void node_sum_kernel() {
    int i = blockIdx.x * blockDim.x + threadIdx.x;
    if (i >= BB * TT) return;
    int b = i / TT;
    unsigned long long p = g_colmax[i];
    unsigned int n = (unsigned int)(p & 0xffffffffu);
    int bn = b * NNODE + n;
    float m = funkey((unsigned int)(p >> 32));
    atomicAdd(&g_Z[bn], expf(m - funkey(g_Mkey[bn])));
}

__global__ void att_scatter_kernel(float* __restrict__ att) {
    int i = blockIdx.x * blockDim.x + threadIdx.x;
    if (i >= BB * TT) return;
    int b = i / TT;
    int t = i % TT;
    unsigned long long p = g_colmax[i];
    unsigned int n = (unsigned int)(p & 0xffffffffu);
    int bn = b * NNODE + n;
    float m = funkey((unsigned int)(p >> 32));
    float w = expf(m - funkey(g_Mkey[bn])) / g_Z[bn];
    att[(long)bn * TT + t] = w;
}

__global__ void outpre_scatter_kernel() {
    int i = blockIdx.x;
    int b = i / TT;
    unsigned long long p = g_colmax[i];
    unsigned int n = (unsigned int)(p & 0xffffffffu);
    int bn = b * NNODE + n;
    float m = funkey((unsigned int)(p >> 32));
    float w = expf(m - funkey(g_Mkey[bn])) / g_Z[bn];
    const float* vrow = g_v + (long)i * CC;
    float* orow = g_op + (long)bn * CC;
    for (int c = threadIdx.x; c < CC; c += blockDim.x)
        atomicAdd(&orow[c], w * vrow[c]);
}

// ============================ launch ============================
extern "C" void kernel_launch(void* const* d_in, const int* in_sizes, int n_in,
                              void* d_out, int out_size)
{
    const float* x    = (const float*)d_in[0];
    const float* Wq   = (const float*)d_in[1];
    const float* bq   = (const float*)d_in[2];
    const float* Wk   = (const float*)d_in[3];
    const float* Wv   = (const float*)d_in[4];
    const float* Wout = (const float*)d_in[5];
    const float* bout = (const float*)d_in[6];

    float* out = (float*)d_out;
    float* att = out + (long)BB * NNODE * CC;

    float2 *x2, *xT2, *Wq2, *Wk2, *Wv2, *Wo2, *k2, *q2, *op2;
    float *vp, *op;
    unsigned long long* cm;
    cudaGetSymbolAddress((void**)&x2, g_x2);
    cudaGetSymbolAddress((void**)&xT2, g_xT2);
    cudaGetSymbolAddress((void**)&Wq2, g_Wq2);
    cudaGetSymbolAddress((void**)&Wk2, g_Wk2);
    cudaGetSymbolAddress((void**)&Wv2, g_Wv2);
    cudaGetSymbolAddress((void**)&Wo2, g_Wo2);
    cudaGetSymbolAddress((void**)&k2, g_k2);
    cudaGetSymbolAddress((void**)&q2, g_q2);
    cudaGetSymbolAddress((void**)&op2, g_op2);
    cudaGetSymbolAddress((void**)&vp, g_v);
    cudaGetSymbolAddress((void**)&op, g_op);
    cudaGetSymbolAddress((void**)&cm, g_colmax);

    cudaFuncSetAttribute(gemm_mma<2,3>, cudaFuncAttributeMaxDynamicSharedMemorySize, SMEM_SZ);
    cudaFuncSetAttribute(gemm_mma<0,2>, cudaFuncAttributeMaxDynamicSharedMemorySize, SMEM_SZ);
    cudaFuncSetAttribute(gemm_mma<3,3>, cudaFuncAttributeMaxDynamicSharedMemorySize, SMEM_SZ);
    cudaFuncSetAttribute(gemm_mma<4,3>, cudaFuncAttributeMaxDynamicSharedMemorySize, SMEM_SZ);
    cudaFuncSetAttribute(gemm_mma<1,2>, cudaFuncAttributeMaxDynamicSharedMemorySize, SMEM_SZ);

    const float scale = 1.0f / sqrtf((float)CC);

    init_kernel<<<2048, 256>>>();
    cudaMemsetAsync(att, 0, (size_t)BB * NNODE * TT * sizeof(float), 0);

    split2i<<<4096, 256>>>(x, x2, (long)BB * TT * CC);
    transpose_split<<<dim3(TT / 32, CC / 32, BB), dim3(32, 8)>>>(x);
    splitW_all<<<2048, 256>>>(Wq, Wk, Wv, Wout);

    // k = x @ Wk^T -> hilo   (M=16384, N=512, K=512)
    gemm_mma<2,3><<<dim3(4, 128, 1), 256, SMEM_SZ>>>(
        x2, Wk2, nullptr, nullptr, k2, CC, CC, 0, 0, 0, 0.f, nullptr, 0);
    // v = x @ Wv^T -> plain (2-term)
    gemm_mma<0,2><<<dim3(4, 128, 1), 256, SMEM_SZ>>>(
        x2, Wv2, nullptr, vp, nullptr, CC, CC, 0, 0, 0, 0.f, nullptr, 0);
    // q[b] = Wq @ xT[b]^T + bq -> hilo   (M=1024, N=512, K=2048)
    gemm_mma<3,3><<<dim3(4, 8, BB), 256, SMEM_SZ>>>(
        Wq2, xT2, bq, nullptr, q2, CC, TT,
        0, (long)CC * TT, (long)NNODE * CC, 0.f, nullptr, 0);
    // sim[b] = scale * k[b] @ q[b]^T, token-major, fused argmax
    gemm_mma<4,3><<<dim3(NNODE / 128, TT / 128, BB), 256, SMEM_SZ>>>(
        k2, q2, nullptr, nullptr, nullptr, NNODE, CC,
        (long)TT * CC, (long)NNODE * CC, 0, scale, cm, (long)TT);

    node_max_kernel<<<(BB * TT) / 256, 256>>>();
    node_sum_kernel<<<(BB * TT) / 256, 256>>>();
    att_scatter_kernel<<<(BB * TT) / 256, 256>>>(att);
    outpre_scatter_kernel<<<BB * TT, 128>>>();

    split2i<<<2048, 256>>>(op, op2, (long)BB * NNODE * CC);
    // out = outpre @ Wout^T + bout (2-term)  (M=8192, N=512, K=512)
    gemm_mma<1,2><<<dim3(4, 64, 1), 256, SMEM_SZ>>>(
        op2, Wo2, bout, out, nullptr, CC, CC, 0, 0, 0, 0.f, nullptr, 0);
}

// round 6
// speedup vs baseline: 1.7028x; 1.7028x over previous
#include <cuda_runtime.h>
#include <cuda_fp16.h>
#include <math.h>
#include <stdint.h>

#define BB 8
#define TT 2048
#define CC 512
#define NNODE 1024

// ============================ scratch (static) ============================
#define AL __align__(128)
__device__ AL __half g_xh[BB * TT * CC];      // 17MB each
__device__ AL __half g_xl[BB * TT * CC];
__device__ AL __half g_xTh[BB * CC * TT];
__device__ AL __half g_xTl[BB * CC * TT];
__device__ AL __half g_Wqh[NNODE * TT];
__device__ AL __half g_Wql[NNODE * TT];
__device__ AL __half g_Wkh[CC * CC];
__device__ AL __half g_Wkl[CC * CC];
__device__ AL __half g_Wvh[CC * CC];
__device__ AL __half g_Wvl[CC * CC];
__device__ AL __half g_Woh[CC * CC];
__device__ AL __half g_Wol[CC * CC];
__device__ AL __half g_kh[BB * TT * CC];
__device__ AL __half g_kl[BB * TT * CC];
__device__ AL __half g_qh[BB * NNODE * CC];
__device__ AL __half g_ql[BB * NNODE * CC];
__device__ AL __half g_oph[BB * NNODE * CC];
__device__ AL __half g_opl[BB * NNODE * CC];
__device__ AL float g_v[BB * TT * CC];        // 33MB
__device__ AL float g_op[BB * NNODE * CC];    // 33MB
__device__ AL unsigned long long g_colmax[BB * TT];
__device__ AL unsigned int g_Mkey[BB * NNODE];
__device__ AL float g_Z[BB * NNODE];

// ============================ helpers ============================
__device__ __forceinline__ unsigned int fkey(float f) {
    unsigned int u = __float_as_uint(f);
    return (u & 0x80000000u) ? ~u : (u | 0x80000000u);
}
__device__ __forceinline__ float funkey(unsigned int u) {
    unsigned int v = (u & 0x80000000u) ? (u & 0x7fffffffu) : ~u;
    return __uint_as_float(v);
}
__device__ __forceinline__ uint32_t smem_u32(const void* p) {
    uint32_t a;
    asm("{ .reg .u64 t; cvta.to.shared.u64 t, %1; cvt.u32.u64 %0, t; }" : "=r"(a) : "l"(p));
    return a;
}
__device__ __forceinline__ void cp16(uint32_t dst, const void* src) {
    asm volatile("cp.async.cg.shared.global [%0], [%1], 16;" :: "r"(dst), "l"(src) : "memory");
}
__device__ __forceinline__ void cp_commit() {
    asm volatile("cp.async.commit_group;" ::: "memory");
}
template <int N> __device__ __forceinline__ void cp_wait() {
    asm volatile("cp.async.wait_group %0;" :: "n"(N) : "memory");
}
// fp16 mma with fp32 accumulate (portable ISA, sm_80+)
__device__ __forceinline__ void mma16(float* d,
                                      unsigned a0, unsigned a1, unsigned a2, unsigned a3,
                                      unsigned b0, unsigned b1) {
    asm volatile(
        "mma.sync.aligned.m16n8k16.row.col.f32.f16.f16.f32 "
        "{%0,%1,%2,%3},{%4,%5,%6,%7},{%8,%9},{%0,%1,%2,%3};"
        : "+f"(d[0]), "+f"(d[1]), "+f"(d[2]), "+f"(d[3])
        : "r"(a0), "r"(a1), "r"(a2), "r"(a3), "r"(b0), "r"(b1));
}
__device__ __forceinline__ void ldmx4(unsigned& r0, unsigned& r1, unsigned& r2, unsigned& r3,
                                      uint32_t addr) {
    asm volatile("ldmatrix.sync.aligned.m8n8.x4.shared.b16 {%0,%1,%2,%3}, [%4];"
                 : "=r"(r0), "=r"(r1), "=r"(r2), "=r"(r3) : "r"(addr));
}

// ============================ fp16 3-split mma.sync NT GEMM ============================
// C[m,n] = sum_k (Ah+Al)[m,k]*(Bh+Bl)[n,k]  (lo*lo dropped; fp16 h/l planes)
// Block 128x128, BK=32 halves, 8 warps 2(m) x 4(n), warp tile 64x32.
// EPI: 0 plain->Cp, 1 plain+colbias->Cp, 2 hilo->Ch/Cl, 3 hilo+rowbias->Ch/Cl, 4 argmax->colmax
static const int SROWB = 80;                        // padded row bytes (32 halves + 16B pad)
static const int TILE_B = 128 * SROWB;              // 10240
static const int STAGE_B = 4 * TILE_B;              // 40960 (Ah, Al, Bh, Bl)
static const int RED_OFF = 2 * STAGE_B;             // 81920
static const int SMEM_SZ = RED_OFF + 1024;          // 82944

template <int EPI>
__global__ __launch_bounds__(256, 2) void gemm_mma(
    const __half* __restrict__ Ahp, const __half* __restrict__ Alp,
    const __half* __restrict__ Bhp, const __half* __restrict__ Blp,
    const float* __restrict__ bias,
    float* __restrict__ Cp, __half* __restrict__ Ch, __half* __restrict__ Cl,
    int Nd, int K,
    long sAz, long sBz, long sCz,
    float scale, unsigned long long* colmax, long sMz)
{
    extern __shared__ __align__(16) char smem[];
    const uint32_t sb = smem_u32(smem);
    const int tid = threadIdx.x;
    const int lane = tid & 31;
    const int wid = tid >> 5;
    const int wm = wid >> 2;            // 0..1
    const int wn = wid & 3;             // 0..3
    const int grp = lane >> 2;          // 0..7
    const int qd = lane & 3;            // 0..3
    const int z = blockIdx.z;
    const long m0 = (long)blockIdx.y * 128;
    const long n0 = (long)blockIdx.x * 128;

    // ---- loader: 2048 x 16B chunks per stage (4 tiles x 128 rows x 4 chunks) ----
    const __half* pT[4] = { Ahp + z * sAz + m0 * K, Alp + z * sAz + m0 * K,
                            Bhp + z * sBz + n0 * K, Blp + z * sBz + n0 * K };
    const __half* src[8];
    uint32_t dst[8];
#pragma unroll
    for (int i = 0; i < 8; i++) {
        int w = i * 256 + tid;          // 0..2047
        int tile = w >> 9;              // 512 chunks per tile
        int row = (w >> 2) & 127;
        int ch = w & 3;
        src[i] = pT[tile] + (long)row * K + ch * 8;
        dst[i] = tile * TILE_B + row * SROWB + ch * 16;
    }

    const int nKB = K >> 5;             // BK = 32 halves

#pragma unroll
    for (int i = 0; i < 8; i++) cp16(sb + dst[i], src[i]);
    cp_commit();

    float acc[4][4][4];
#pragma unroll
    for (int mf = 0; mf < 4; mf++)
#pragma unroll
        for (int nf = 0; nf < 4; nf++)
#pragma unroll
            for (int r = 0; r < 4; r++) acc[mf][nf][r] = 0.f;

    // ldmatrix per-thread address components (row = lane&15, col-half = (lane>>4)*8)
    const int lrow = lane & 15;
    const int lcol = (lane >> 4) * 8;   // halves

    for (int kb = 0; kb < nKB; kb++) {
        if (kb + 1 < nKB) {
            uint32_t so = ((kb + 1) & 1) * STAGE_B;
            const long ko = (long)(kb + 1) * 32;
#pragma unroll
            for (int i = 0; i < 8; i++) cp16(sb + so + dst[i], src[i] + ko);
            cp_commit();
            cp_wait<1>();
        } else {
            cp_wait<0>();
        }
        __syncthreads();

        const uint32_t stg = sb + (kb & 1) * STAGE_B;
        const uint32_t sAh = stg, sAl = stg + TILE_B;
        const uint32_t sBh = stg + 2 * TILE_B, sBl = stg + 3 * TILE_B;

#pragma unroll
        for (int ks = 0; ks < 2; ks++) {
            const int k0 = ks * 16;     // halves
            const uint32_t cofs = (lcol + k0) * 2;
            // B fragments: 2 nf-pairs x (hi, lo)
            unsigned rbh[2][4], rbl[2][4];
#pragma unroll
            for (int nfp = 0; nfp < 2; nfp++) {
                uint32_t ro = (uint32_t)(wn * 32 + nfp * 16 + lrow) * SROWB + cofs;
                ldmx4(rbh[nfp][0], rbh[nfp][1], rbh[nfp][2], rbh[nfp][3], sBh + ro);
                ldmx4(rbl[nfp][0], rbl[nfp][1], rbl[nfp][2], rbl[nfp][3], sBl + ro);
            }
#pragma unroll
            for (int mf = 0; mf < 4; mf++) {
                uint32_t ro = (uint32_t)(wm * 64 + mf * 16 + lrow) * SROWB + cofs;
                unsigned ah0, ah1, ah2, ah3, al0, al1, al2, al3;
                ldmx4(ah0, ah1, ah2, ah3, sAh + ro);
                ldmx4(al0, al1, al2, al3, sAl + ro);
#pragma unroll
                for (int nfp = 0; nfp < 2; nfp++) {
#pragma unroll
                    for (int sub = 0; sub < 2; sub++) {
                        float* d = acc[mf][nfp * 2 + sub];
                        unsigned bh0 = rbh[nfp][sub], bh1 = rbh[nfp][sub + 2];
                        unsigned bl0 = rbl[nfp][sub], bl1 = rbl[nfp][sub + 2];
                        mma16(d, ah0, ah1, ah2, ah3, bh0, bh1);
                        mma16(d, ah0, ah1, ah2, ah3, bl0, bl1);
                        mma16(d, al0, al1, al2, al3, bh0, bh1);
                    }
                }
            }
        }
        __syncthreads();
    }

    // ---------------- epilogue (D fragment: rows grp/grp+8, cols 2qd,2qd+1) ----------------
    if constexpr (EPI == 4) {
        unsigned long long* red = (unsigned long long*)(smem + RED_OFF);
        if (tid < 128) red[tid] = 0ull;
        __syncthreads();
#pragma unroll
        for (int mf = 0; mf < 4; mf++) {
#pragma unroll
            for (int half = 0; half < 2; half++) {
                int lr = wm * 64 + mf * 16 + grp + half * 8;
                float bv = -INFINITY; int bc = 0;
#pragma unroll
                for (int nf = 0; nf < 4; nf++) {
#pragma unroll
                    for (int c = 0; c < 2; c++) {
                        float vv = acc[mf][nf][half * 2 + c];
                        int col = (int)n0 + wn * 32 + nf * 8 + qd * 2 + c;
                        if (vv > bv) { bv = vv; bc = col; }
                    }
                }
                unsigned long long pack =
                    ((unsigned long long)fkey(bv * scale) << 32) | (unsigned int)bc;
                unsigned long long o;
                o = __shfl_xor_sync(0xffffffffu, pack, 1); if (o > pack) pack = o;
                o = __shfl_xor_sync(0xffffffffu, pack, 2); if (o > pack) pack = o;
                if (qd == 0) atomicMax(&red[lr], pack);
            }
        }
        __syncthreads();
        if (tid < 128)
            atomicMax(&colmax[z * sMz + m0 + tid], red[tid]);
    } else {
#pragma unroll
        for (int mf = 0; mf < 4; mf++) {
#pragma unroll
            for (int half = 0; half < 2; half++) {
                long row = m0 + wm * 64 + mf * 16 + grp + half * 8;
                float rb = 0.f;
                if constexpr (EPI == 3) rb = bias[row];
                long base = z * sCz + row * (long)Nd + n0 + wn * 32 + qd * 2;
#pragma unroll
                for (int nf = 0; nf < 4; nf++) {
                    float v0 = acc[mf][nf][half * 2 + 0];
                    float v1 = acc[mf][nf][half * 2 + 1];
                    long off = base + nf * 8;
                    if constexpr (EPI == 0 || EPI == 1) {
                        if constexpr (EPI == 1) {
                            v0 += bias[n0 + wn * 32 + nf * 8 + qd * 2 + 0];
                            v1 += bias[n0 + wn * 32 + nf * 8 + qd * 2 + 1];
                        }
                        *reinterpret_cast<float2*>(&Cp[off]) = make_float2(v0, v1);
                    } else {
                        v0 += rb; v1 += rb;
                        __half h0 = __float2half_rn(v0);
                        __half h1 = __float2half_rn(v1);
                        __half l0 = __float2half_rn(v0 - __half2float(h0));
                        __half l1 = __float2half_rn(v1 - __half2float(h1));
                        *reinterpret_cast<__half2*>(&Ch[off]) = __halves2half2(h0, h1);
                        *reinterpret_cast<__half2*>(&Cl[off]) = __halves2half2(l0, l1);
                    }
                }
            }
        }
    }
}

// ============================ small kernels ============================
__global__ void init_kernel() {
    int i = blockIdx.x * blockDim.x + threadIdx.x;
    int stride = gridDim.x * blockDim.x;
    for (int j = i; j < BB * TT; j += stride) g_colmax[j] = 0ull;
    for (int j = i; j < BB * NNODE; j += stride) { g_Mkey[j] = 0u; g_Z[j] = 0.f; }
    for (int j = i; j < BB * NNODE * CC; j += stride) g_op[j] = 0.f;
}

__device__ __forceinline__ void split_h(float v, __half& h, __half& l) {
    h = __float2half_rn(v);
    l = __float2half_rn(v - __half2float(h));
}

__global__ void split2h(const float* __restrict__ in, __half* __restrict__ hp,
                        __half* __restrict__ lp, long n) {
    long i = (long)blockIdx.x * blockDim.x + threadIdx.x;
    long stride = (long)gridDim.x * blockDim.x;
    for (long j = i; j < n; j += stride) {
        __half h, l;
        split_h(in[j], h, l);
        hp[j] = h; lp[j] = l;
    }
}

__global__ void transpose_split(const float* __restrict__ x) {
    __shared__ float tile[32][33];
    int z = blockIdx.z;
    int t0 = blockIdx.x * 32, c0 = blockIdx.y * 32;
    int tx = threadIdx.x, ty = threadIdx.y;
#pragma unroll
    for (int i = 0; i < 32; i += 8)
        tile[ty + i][tx] = x[((long)z * TT + t0 + ty + i) * CC + c0 + tx];
    __syncthreads();
#pragma unroll
    for (int i = 0; i < 32; i += 8) {
        long o = ((long)z * CC + c0 + ty + i) * TT + t0 + tx;
        __half h, l;
        split_h(tile[tx][ty + i], h, l);
        g_xTh[o] = h; g_xTl[o] = l;
    }
}

__global__ void splitW_all(const float* __restrict__ Wq, const float* __restrict__ Wk,
                           const float* __restrict__ Wv, const float* __restrict__ Wo) {
    const long nq = (long)NNODE * TT, nw = (long)CC * CC;
    long i = (long)blockIdx.x * blockDim.x + threadIdx.x;
    long stride = (long)gridDim.x * blockDim.x;
    long total = nq + 3 * nw;
    for (long j = i; j < total; j += stride) {
        float v; __half *dh, *dl; long o;
        if (j < nq) { o = j; v = Wq[o]; dh = g_Wqh; dl = g_Wql; }
        else if (j < nq + nw) { o = j - nq; v = Wk[o]; dh = g_Wkh; dl = g_Wkl; }
        else if (j < nq + 2 * nw) { o = j - nq - nw; v = Wv[o]; dh = g_Wvh; dl = g_Wvl; }
        else { o = j - nq - 2 * nw; v = Wo[o]; dh = g_Woh; dl = g_Wol; }
        __half h, l;
        split_h(v, h, l);
        dh[o] = h; dl[o] = l;
    }
}

__global__ void node_max_kernel() {
    int i = blockIdx.x * blockDim.x + threadIdx.x;
    if (i >= BB * TT) return;
    int b = i / TT;
    unsigned long long p = g_colmax[i];
    unsigned int n = (unsigned int)(p & 0xffffffffu);
    atomicMax(&g_Mkey[b * NNODE + n], (unsigned int)(p >> 32));
}

__global__ void node_sum_kernel() {
    int i = blockIdx.x * blockDim.x + threadIdx.x;
    if (i >= BB * TT) return;
    int b = i / TT;
    unsigned long long p = g_colmax[i];
    unsigned int n = (unsigned int)(p & 0xffffffffu);
    int bn = b * NNODE + n;
    float m = funkey((unsigned int)(p >> 32));
    atomicAdd(&g_Z[bn], expf(m - funkey(g_Mkey[bn])));
}

__global__ void att_scatter_kernel(float* __restrict__ att) {
    int i = blockIdx.x * blockDim.x + threadIdx.x;
    if (i >= BB * TT) return;
    int b = i / TT;
    int t = i % TT;
    unsigned long long p = g_colmax[i];
    unsigned int n = (unsigned int)(p & 0xffffffffu);
    int bn = b * NNODE + n;
    float m = funkey((unsigned int)(p >> 32));
    float w = expf(m - funkey(g_Mkey[bn])) / g_Z[bn];
    att[(long)bn * TT + t] = w;
}

__global__ void outpre_scatter_kernel() {
    int i = blockIdx.x;
    int b = i / TT;
    unsigned long long p = g_colmax[i];
    unsigned int n = (unsigned int)(p & 0xffffffffu);
    int bn = b * NNODE + n;
    float m = funkey((unsigned int)(p >> 32));
    float w = expf(m - funkey(g_Mkey[bn])) / g_Z[bn];
    const float* vrow = g_v + (long)i * CC;
    float* orow = g_op + (long)bn * CC;
    for (int c = threadIdx.x; c < CC; c += blockDim.x)
        atomicAdd(&orow[c], w * vrow[c]);
}

// ============================ launch ============================
extern "C" void kernel_launch(void* const* d_in, const int* in_sizes, int n_in,
                              void* d_out, int out_size)
{
    const float* x    = (const float*)d_in[0];
    const float* Wq   = (const float*)d_in[1];
    const float* bq   = (const float*)d_in[2];
    const float* Wk   = (const float*)d_in[3];
    const float* Wv   = (const float*)d_in[4];
    const float* Wout = (const float*)d_in[5];
    const float* bout = (const float*)d_in[6];

    float* out = (float*)d_out;
    float* att = out + (long)BB * NNODE * CC;

    __half *xh, *xl, *xTh, *xTl, *Wqh, *Wql, *Wkh, *Wkl, *Wvh, *Wvl, *Woh, *Wol;
    __half *kh, *kl, *qh, *ql, *oph, *opl;
    float *vp, *op;
    unsigned long long* cm;
    cudaGetSymbolAddress((void**)&xh, g_xh);   cudaGetSymbolAddress((void**)&xl, g_xl);
    cudaGetSymbolAddress((void**)&xTh, g_xTh); cudaGetSymbolAddress((void**)&xTl, g_xTl);
    cudaGetSymbolAddress((void**)&Wqh, g_Wqh); cudaGetSymbolAddress((void**)&Wql, g_Wql);
    cudaGetSymbolAddress((void**)&Wkh, g_Wkh); cudaGetSymbolAddress((void**)&Wkl, g_Wkl);
    cudaGetSymbolAddress((void**)&Wvh, g_Wvh); cudaGetSymbolAddress((void**)&Wvl, g_Wvl);
    cudaGetSymbolAddress((void**)&Woh, g_Woh); cudaGetSymbolAddress((void**)&Wol, g_Wol);
    cudaGetSymbolAddress((void**)&kh, g_kh);   cudaGetSymbolAddress((void**)&kl, g_kl);
    cudaGetSymbolAddress((void**)&qh, g_qh);   cudaGetSymbolAddress((void**)&ql, g_ql);
    cudaGetSymbolAddress((void**)&oph, g_oph); cudaGetSymbolAddress((void**)&opl, g_opl);
    cudaGetSymbolAddress((void**)&vp, g_v);
    cudaGetSymbolAddress((void**)&op, g_op);
    cudaGetSymbolAddress((void**)&cm, g_colmax);

    cudaFuncSetAttribute(gemm_mma<0>, cudaFuncAttributeMaxDynamicSharedMemorySize, SMEM_SZ);
    cudaFuncSetAttribute(gemm_mma<1>, cudaFuncAttributeMaxDynamicSharedMemorySize, SMEM_SZ);
    cudaFuncSetAttribute(gemm_mma<2>, cudaFuncAttributeMaxDynamicSharedMemorySize, SMEM_SZ);
    cudaFuncSetAttribute(gemm_mma<3>, cudaFuncAttributeMaxDynamicSharedMemorySize, SMEM_SZ);
    cudaFuncSetAttribute(gemm_mma<4>, cudaFuncAttributeMaxDynamicSharedMemorySize, SMEM_SZ);

    const float scale = 1.0f / sqrtf((float)CC);

    init_kernel<<<2048, 256>>>();
    cudaMemsetAsync(att, 0, (size_t)BB * NNODE * TT * sizeof(float), 0);

    split2h<<<4096, 256>>>(x, xh, xl, (long)BB * TT * CC);
    transpose_split<<<dim3(TT / 32, CC / 32, BB), dim3(32, 8)>>>(x);
    splitW_all<<<2048, 256>>>(Wq, Wk, Wv, Wout);

    // k = x @ Wk^T -> hilo   (M=16384, N=512, K=512)
    gemm_mma<2><<<dim3(4, 128, 1), 256, SMEM_SZ>>>(
        xh, xl, Wkh, Wkl, nullptr, nullptr, kh, kl, CC, CC, 0, 0, 0, 0.f, nullptr, 0);
    // v = x @ Wv^T -> plain
    gemm_mma<0><<<dim3(4, 128, 1), 256, SMEM_SZ>>>(
        xh, xl, Wvh, Wvl, nullptr, vp, nullptr, nullptr, CC, CC, 0, 0, 0, 0.f, nullptr, 0);
    // q[b] = Wq @ xT[b]^T + bq -> hilo   (M=1024, N=512, K=2048)
    gemm_mma<3><<<dim3(4, 8, BB), 256, SMEM_SZ>>>(
        Wqh, Wql, xTh, xTl, bq, nullptr, qh, ql, CC, TT,
        0, (long)CC * TT, (long)NNODE * CC, 0.f, nullptr, 0);
    // sim[b] = scale * k[b] @ q[b]^T, token-major, fused argmax
    gemm_mma<4><<<dim3(NNODE / 128, TT / 128, BB), 256, SMEM_SZ>>>(
        kh, kl, qh, ql, nullptr, nullptr, nullptr, nullptr, NNODE, CC,
        (long)TT * CC, (long)NNODE * CC, 0, scale, cm, (long)TT);

    node_max_kernel<<<(BB * TT) / 256, 256>>>();
    node_sum_kernel<<<(BB * TT) / 256, 256>>>();
    att_scatter_kernel<<<(BB * TT) / 256, 256>>>(att);
    outpre_scatter_kernel<<<BB * TT, 128>>>();

    split2h<<<2048, 256>>>(op, oph, opl, (long)BB * NNODE * CC);
    // out = outpre @ Wout^T + bout   (M=8192, N=512, K=512)
    gemm_mma<1><<<dim3(4, 64, 1), 256, SMEM_SZ>>>(
        oph, opl, Woh, Wol, bout, out, nullptr, nullptr, CC, CC, 0, 0, 0, 0.f, nullptr, 0);
}

// round 8
// speedup vs baseline: 1.8267x; 1.0728x over previous
#include <cuda_runtime.h>
#include <cuda_fp16.h>
#include <math.h>
#include <stdint.h>

#define BB 8
#define TT 2048
#define CC 512
#define NNODE 1024

// ============================ scratch (static) ============================
#define AL __align__(128)
__device__ AL __half g_xh[BB * TT * CC];
__device__ AL __half g_xl[BB * TT * CC];
__device__ AL __half g_xTh[BB * CC * TT];
__device__ AL __half g_xTl[BB * CC * TT];
__device__ AL __half g_Wqh[NNODE * TT];
__device__ AL __half g_Wql[NNODE * TT];
__device__ AL __half g_Wkh[CC * CC];
__device__ AL __half g_Wkl[CC * CC];
__device__ AL __half g_Wvh[CC * CC];
__device__ AL __half g_Wvl[CC * CC];
__device__ AL __half g_Woh[CC * CC];
__device__ AL __half g_Wol[CC * CC];
__device__ AL __half g_kh[BB * TT * CC];
__device__ AL __half g_kl[BB * TT * CC];
__device__ AL __half g_qh[BB * NNODE * CC];
__device__ AL __half g_ql[BB * NNODE * CC];
__device__ AL __half g_oph[BB * NNODE * CC];
__device__ AL __half g_opl[BB * NNODE * CC];
__device__ AL float g_v[BB * TT * CC];
__device__ AL float g_op[BB * NNODE * CC];
__device__ AL unsigned long long g_colmax[BB * TT];
__device__ AL unsigned int g_Mkey[BB * NNODE];
__device__ AL float g_Z[BB * NNODE];

// ============================ helpers ============================
__device__ __forceinline__ unsigned int fkey(float f) {
    unsigned int u = __float_as_uint(f);
    return (u & 0x80000000u) ? ~u : (u | 0x80000000u);
}
__device__ __forceinline__ float funkey(unsigned int u) {
    unsigned int v = (u & 0x80000000u) ? (u & 0x7fffffffu) : ~u;
    return __uint_as_float(v);
}
__device__ __forceinline__ uint32_t smem_u32(const void* p) {
    uint32_t a;
    asm("{ .reg .u64 t; cvta.to.shared.u64 t, %1; cvt.u32.u64 %0, t; }" : "=r"(a) : "l"(p));
    return a;
}
__device__ __forceinline__ void cp16(uint32_t dst, const void* src) {
    asm volatile("cp.async.cg.shared.global [%0], [%1], 16;" :: "r"(dst), "l"(src) : "memory");
}
__device__ __forceinline__ void cp_commit() {
    asm volatile("cp.async.commit_group;" ::: "memory");
}
template <int N> __device__ __forceinline__ void cp_wait() {
    asm volatile("cp.async.wait_group %0;" :: "n"(N) : "memory");
}
__device__ __forceinline__ void mma16(float* d,
                                      unsigned a0, unsigned a1, unsigned a2, unsigned a3,
                                      unsigned b0, unsigned b1) {
    asm volatile(
        "mma.sync.aligned.m16n8k16.row.col.f32.f16.f16.f32 "
        "{%0,%1,%2,%3},{%4,%5,%6,%7},{%8,%9},{%0,%1,%2,%3};"
        : "+f"(d[0]), "+f"(d[1]), "+f"(d[2]), "+f"(d[3])
        : "r"(a0), "r"(a1), "r"(a2), "r"(a3), "r"(b0), "r"(b1));
}
__device__ __forceinline__ void ldmx4(unsigned& r0, unsigned& r1, unsigned& r2, unsigned& r3,
                                      uint32_t addr) {
    asm volatile("ldmatrix.sync.aligned.m8n8.x4.shared.b16 {%0,%1,%2,%3}, [%4];"
                 : "=r"(r0), "=r"(r1), "=r"(r2), "=r"(r3) : "r"(addr));
}
__device__ __forceinline__ void split_h(float v, __half& h, __half& l) {
    h = __float2half_rn(v);
    l = __float2half_rn(v - __half2float(h));
}
__device__ __forceinline__ unsigned packh2(__half a, __half b) {
    __half2 t = __halves2half2(a, b);
    return *reinterpret_cast<unsigned*>(&t);
}

// ============================ fp16 split mma.sync NT GEMM ============================
// NTERM=3: ah*bh + ah*bl + al*bh.  NTERM=2: ah*bh + al*bh (B-lo dropped, tile not even loaded).
// Block 128x128, BK=32 halves, 8 warps 2(m) x 4(n), warp tile 64x32.
// EPI: 0 plain->Cp, 1 plain+colbias->Cp, 2 hilo->Ch/Cl, 3 hilo+rowbias->Ch/Cl, 4 argmax->colmax
static const int SROWB = 80;                        // padded row bytes (32 halves + 16B pad)
static const int TILE_B = 128 * SROWB;              // 10240
static const int STAGE_B = 4 * TILE_B;              // 40960 (Ah, Al, Bh, Bl)
static const int RED_OFF = 2 * STAGE_B;             // 81920
static const int SMEM_SZ = RED_OFF + 1024;          // 82944

template <int EPI, int NTERM>
__global__ __launch_bounds__(256, 2) void gemm_mma(
    const __half* __restrict__ Ahp, const __half* __restrict__ Alp,
    const __half* __restrict__ Bhp, const __half* __restrict__ Blp,
    const float* __restrict__ bias,
    float* __restrict__ Cp, __half* __restrict__ Ch, __half* __restrict__ Cl,
    int Nd, int K,
    long sAz, long sBz, long sCz,
    float scale, unsigned long long* colmax, long sMz)
{
    extern __shared__ __align__(16) char smem[];
    const uint32_t sb = smem_u32(smem);
    const int tid = threadIdx.x;
    const int lane = tid & 31;
    const int wid = tid >> 5;
    const int wm = wid >> 2;
    const int wn = wid & 3;
    const int grp = lane >> 2;
    const int qd = lane & 3;
    const int z = blockIdx.z;
    const long m0 = (long)blockIdx.y * 128;
    const long n0 = (long)blockIdx.x * 128;

    const __half* pT[4] = { Ahp + z * sAz + m0 * K, Alp + z * sAz + m0 * K,
                            Bhp + z * sBz + n0 * K, Blp + z * sBz + n0 * K };
    const __half* src[8];
    uint32_t dst[8];
#pragma unroll
    for (int i = 0; i < 8; i++) {
        int w = i * 256 + tid;
        int tile = w >> 9;
        int row = (w >> 2) & 127;
        int ch = w & 3;
        src[i] = pT[tile] + (long)row * K + ch * 8;
        dst[i] = tile * TILE_B + row * SROWB + ch * 16;
    }

    const int nKB = K >> 5;

#pragma unroll
    for (int i = 0; i < 8; i++)
        if (NTERM == 3 || i < 6) cp16(sb + dst[i], src[i]);
    cp_commit();

    float acc[4][4][4];
#pragma unroll
    for (int mf = 0; mf < 4; mf++)
#pragma unroll
        for (int nf = 0; nf < 4; nf++)
#pragma unroll
            for (int r = 0; r < 4; r++) acc[mf][nf][r] = 0.f;

    const int lrow = lane & 15;
    const int lcol = (lane >> 4) * 8;

    for (int kb = 0; kb < nKB; kb++) {
        if (kb + 1 < nKB) {
            uint32_t so = ((kb + 1) & 1) * STAGE_B;
            const long ko = (long)(kb + 1) * 32;
#pragma unroll
            for (int i = 0; i < 8; i++)
                if (NTERM == 3 || i < 6) cp16(sb + so + dst[i], src[i] + ko);
            cp_commit();
            cp_wait<1>();
        } else {
            cp_wait<0>();
        }
        __syncthreads();

        const uint32_t stg = sb + (kb & 1) * STAGE_B;
        const uint32_t sAh = stg, sAl = stg + TILE_B;
        const uint32_t sBh = stg + 2 * TILE_B, sBl = stg + 3 * TILE_B;

#pragma unroll
        for (int ks = 0; ks < 2; ks++) {
            const int k0 = ks * 16;
            const uint32_t cofs = (lcol + k0) * 2;
            unsigned rbh[2][4], rbl[2][4];
#pragma unroll
            for (int nfp = 0; nfp < 2; nfp++) {
                uint32_t ro = (uint32_t)(wn * 32 + nfp * 16 + lrow) * SROWB + cofs;
                ldmx4(rbh[nfp][0], rbh[nfp][1], rbh[nfp][2], rbh[nfp][3], sBh + ro);
                if (NTERM == 3)
                    ldmx4(rbl[nfp][0], rbl[nfp][1], rbl[nfp][2], rbl[nfp][3], sBl + ro);
            }
#pragma unroll
            for (int mf = 0; mf < 4; mf++) {
                uint32_t ro = (uint32_t)(wm * 64 + mf * 16 + lrow) * SROWB + cofs;
                unsigned ah0, ah1, ah2, ah3, al0, al1, al2, al3;
                ldmx4(ah0, ah1, ah2, ah3, sAh + ro);
                ldmx4(al0, al1, al2, al3, sAl + ro);
#pragma unroll
                for (int nfp = 0; nfp < 2; nfp++) {
#pragma unroll
                    for (int sub = 0; sub < 2; sub++) {
                        float* d = acc[mf][nfp * 2 + sub];
                        unsigned bh0 = rbh[nfp][sub], bh1 = rbh[nfp][sub + 2];
                        mma16(d, ah0, ah1, ah2, ah3, bh0, bh1);
                        if (NTERM == 3) {
                            unsigned bl0 = rbl[nfp][sub], bl1 = rbl[nfp][sub + 2];
                            mma16(d, ah0, ah1, ah2, ah3, bl0, bl1);
                        }
                        mma16(d, al0, al1, al2, al3, bh0, bh1);
                    }
                }
            }
        }
        __syncthreads();
    }

    // ---------------- epilogue ----------------
    if constexpr (EPI == 4) {
        unsigned long long* red = (unsigned long long*)(smem + RED_OFF);
        if (tid < 128) red[tid] = 0ull;
        __syncthreads();
#pragma unroll
        for (int mf = 0; mf < 4; mf++) {
#pragma unroll
            for (int half = 0; half < 2; half++) {
                int lr = wm * 64 + mf * 16 + grp + half * 8;
                float bv = -INFINITY; int bc = 0;
#pragma unroll
                for (int nf = 0; nf < 4; nf++) {
#pragma unroll
                    for (int c = 0; c < 2; c++) {
                        float vv = acc[mf][nf][half * 2 + c];
                        int col = (int)n0 + wn * 32 + nf * 8 + qd * 2 + c;
                        if (vv > bv) { bv = vv; bc = col; }
                    }
                }
                unsigned long long pack =
                    ((unsigned long long)fkey(bv * scale) << 32) | (unsigned int)bc;
                unsigned long long o;
                o = __shfl_xor_sync(0xffffffffu, pack, 1); if (o > pack) pack = o;
                o = __shfl_xor_sync(0xffffffffu, pack, 2); if (o > pack) pack = o;
                if (qd == 0) atomicMax(&red[lr], pack);
            }
        }
        __syncthreads();
        if (tid < 128)
            atomicMax(&colmax[z * sMz + m0 + tid], red[tid]);
    } else {
#pragma unroll
        for (int mf = 0; mf < 4; mf++) {
#pragma unroll
            for (int half = 0; half < 2; half++) {
                long row = m0 + wm * 64 + mf * 16 + grp + half * 8;
                float rb = 0.f;
                if constexpr (EPI == 3) rb = bias[row];
                long base = z * sCz + row * (long)Nd + n0 + wn * 32 + qd * 2;
#pragma unroll
                for (int nf = 0; nf < 4; nf++) {
                    float v0 = acc[mf][nf][half * 2 + 0];
                    float v1 = acc[mf][nf][half * 2 + 1];
                    long off = base + nf * 8;
                    if constexpr (EPI == 0 || EPI == 1) {
                        if constexpr (EPI == 1) {
                            v0 += bias[n0 + wn * 32 + nf * 8 + qd * 2 + 0];
                            v1 += bias[n0 + wn * 32 + nf * 8 + qd * 2 + 1];
                        }
                        *reinterpret_cast<float2*>(&Cp[off]) = make_float2(v0, v1);
                    } else {
                        v0 += rb; v1 += rb;
                        __half h0, l0, h1, l1;
                        split_h(v0, h0, l0);
                        split_h(v1, h1, l1);
                        *reinterpret_cast<__half2*>(&Ch[off]) = __halves2half2(h0, h1);
                        *reinterpret_cast<__half2*>(&Cl[off]) = __halves2half2(l0, l1);
                    }
                }
            }
        }
    }
}

// ============================ small kernels ============================
__global__ void init_kernel() {
    int i = blockIdx.x * blockDim.x + threadIdx.x;
    int stride = gridDim.x * blockDim.x;
    for (int j = i; j < BB * TT; j += stride) g_colmax[j] = 0ull;
    for (int j = i; j < BB * NNODE; j += stride) { g_Mkey[j] = 0u; g_Z[j] = 0.f; }
    float4* op4 = reinterpret_cast<float4*>(g_op);
    const int n4 = BB * NNODE * CC / 4;
    for (int j = i; j < n4; j += stride) op4[j] = make_float4(0.f, 0.f, 0.f, 0.f);
}

// fused: x -> (xh, xl) row-major AND (xTh, xTl) transposed, single read of x
__global__ void split_x(const float* __restrict__ x) {
    __shared__ float tile[32][33];
    const int z = blockIdx.z;
    const int t0 = blockIdx.x * 32, c0 = blockIdx.y * 32;
    const int tx = threadIdx.x, ty = threadIdx.y;
#pragma unroll
    for (int i = 0; i < 32; i += 8) {
        long o = ((long)z * TT + t0 + ty + i) * CC + c0 + tx;
        float v = x[o];
        tile[ty + i][tx] = v;
        __half h, l;
        split_h(v, h, l);
        g_xh[o] = h; g_xl[o] = l;
    }
    __syncthreads();
    const int tid = ty * 32 + tx;
    const int cr = tid >> 3;           // 0..31 (c-local)
    const int q = tid & 7;             // 0..7  (t-quad)
    __half hh[4], ll[4];
#pragma unroll
    for (int j = 0; j < 4; j++)
        split_h(tile[4 * q + j][cr], hh[j], ll[j]);
    long ob = ((long)z * CC + c0 + cr) * TT + t0 + 4 * q;
    *reinterpret_cast<uint2*>(&g_xTh[ob]) = make_uint2(packh2(hh[0], hh[1]), packh2(hh[2], hh[3]));
    *reinterpret_cast<uint2*>(&g_xTl[ob]) = make_uint2(packh2(ll[0], ll[1]), packh2(ll[2], ll[3]));
}

__global__ void splitW_all(const float* __restrict__ Wq, const float* __restrict__ Wk,
                           const float* __restrict__ Wv, const float* __restrict__ Wo) {
    const long nq4 = (long)NNODE * TT / 4, nw4 = (long)CC * CC / 4;
    long i = (long)blockIdx.x * blockDim.x + threadIdx.x;
    long stride = (long)gridDim.x * blockDim.x;
    long total = nq4 + 3 * nw4;
    for (long j = i; j < total; j += stride) {
        const float* s; __half *dh, *dl; long o;
        if (j < nq4) { o = j; s = Wq; dh = g_Wqh; dl = g_Wql; }
        else if (j < nq4 + nw4) { o = j - nq4; s = Wk; dh = g_Wkh; dl = g_Wkl; }
        else if (j < nq4 + 2 * nw4) { o = j - nq4 - nw4; s = Wv; dh = g_Wvh; dl = g_Wvl; }
        else { o = j - nq4 - 2 * nw4; s = Wo; dh = g_Woh; dl = g_Wol; }
        float4 v = reinterpret_cast<const float4*>(s)[o];
        __half h0, l0, h1, l1, h2, l2, h3, l3;
        split_h(v.x, h0, l0); split_h(v.y, h1, l1);
        split_h(v.z, h2, l2); split_h(v.w, h3, l3);
        reinterpret_cast<uint2*>(dh)[o] = make_uint2(packh2(h0, h1), packh2(h2, h3));
        reinterpret_cast<uint2*>(dl)[o] = make_uint2(packh2(l0, l1), packh2(l2, l3));
    }
}

__global__ void split2h_v4(const float* __restrict__ in, __half* __restrict__ hp,
                           __half* __restrict__ lp, long n4) {
    long i = (long)blockIdx.x * blockDim.x + threadIdx.x;
    long stride = (long)gridDim.x * blockDim.x;
    for (long j = i; j < n4; j += stride) {
        float4 v = reinterpret_cast<const float4*>(in)[j];
        __half h0, l0, h1, l1, h2, l2, h3, l3;
        split_h(v.x, h0, l0); split_h(v.y, h1, l1);
        split_h(v.z, h2, l2); split_h(v.w, h3, l3);
        reinterpret_cast<uint2*>(hp)[j] = make_uint2(packh2(h0, h1), packh2(h2, h3));
        reinterpret_cast<uint2*>(lp)[j] = make_uint2(packh2(l0, l1), packh2(l2, l3));
    }
}

__global__ void node_max_kernel() {
    int i = blockIdx.x * blockDim.x + threadIdx.x;
    if (i >= BB * TT) return;
    int b = i / TT;
    unsigned long long p = g_colmax[i];
    unsigned int n = (unsigned int)(p & 0xffffffffu);
    atomicMax(&g_Mkey[b * NNODE + n], (unsigned int)(p >> 32));
}

__global__ void node_sum_kernel() {
    int i = blockIdx.x * blockDim.x + threadIdx.x;
    if (i >= BB * TT) return;
    int b = i / TT;
    unsigned long long p = g_colmax[i];
    unsigned int n = (unsigned int)(p & 0xffffffffu);
    int bn = b * NNODE + n;
    float m = funkey((unsigned int)(p >> 32));
    atomicAdd(&g_Z[bn], expf(m - funkey(g_Mkey[bn])));
}

__global__ void att_scatter_kernel(float* __restrict__ att) {
    int i = blockIdx.x * blockDim.x + threadIdx.x;
    if (i >= BB * TT) return;
    int b = i / TT;
    int t = i % TT;
    unsigned long long p = g_colmax[i];
    unsigned int n = (unsigned int)(p & 0xffffffffu);
    int bn = b * NNODE + n;
    float m = funkey((unsigned int)(p >> 32));
    float w = expf(m - funkey(g_Mkey[bn])) / g_Z[bn];
    att[(long)bn * TT + t] = w;
}

__global__ void outpre_scatter_kernel() {
    int i = blockIdx.x;
    int b = i / TT;
    unsigned long long p = g_colmax[i];
    unsigned int n = (unsigned int)(p & 0xffffffffu);
    int bn = b * NNODE + n;
    float m = funkey((unsigned int)(p >> 32));
    float w = expf(m - funkey(g_Mkey[bn])) / g_Z[bn];
    const float4* vrow = reinterpret_cast<const float4*>(g_v + (long)i * CC);
    float* orow = g_op + (long)bn * CC;
    for (int c4 = threadIdx.x; c4 < CC / 4; c4 += blockDim.x) {
        float4 v4 = vrow[c4];
        atomicAdd(&orow[c4 * 4 + 0], w * v4.x);
        atomicAdd(&orow[c4 * 4 + 1], w * v4.y);
        atomicAdd(&orow[c4 * 4 + 2], w * v4.z);
        atomicAdd(&orow[c4 * 4 + 3], w * v4.w);
    }
}

// ============================ launch ============================
extern "C" void kernel_launch(void* const* d_in, const int* in_sizes, int n_in,
                              void* d_out, int out_size)
{
    const float* x    = (const float*)d_in[0];
    const float* Wq   = (const float*)d_in[1];
    const float* bq   = (const float*)d_in[2];
    const float* Wk   = (const float*)d_in[3];
    const float* Wv   = (const float*)d_in[4];
    const float* Wout = (const float*)d_in[5];
    const float* bout = (const float*)d_in[6];

    float* out = (float*)d_out;
    float* att = out + (long)BB * NNODE * CC;

    __half *xh, *xl, *xTh, *xTl, *Wqh, *Wql, *Wkh, *Wkl, *Wvh, *Wvl, *Woh, *Wol;
    __half *kh, *kl, *qh, *ql, *oph, *opl;
    float *vp, *op;
    unsigned long long* cm;
    cudaGetSymbolAddress((void**)&xh, g_xh);   cudaGetSymbolAddress((void**)&xl, g_xl);
    cudaGetSymbolAddress((void**)&xTh, g_xTh); cudaGetSymbolAddress((void**)&xTl, g_xTl);
    cudaGetSymbolAddress((void**)&Wqh, g_Wqh); cudaGetSymbolAddress((void**)&Wql, g_Wql);
    cudaGetSymbolAddress((void**)&Wkh, g_Wkh); cudaGetSymbolAddress((void**)&Wkl, g_Wkl);
    cudaGetSymbolAddress((void**)&Wvh, g_Wvh); cudaGetSymbolAddress((void**)&Wvl, g_Wvl);
    cudaGetSymbolAddress((void**)&Woh, g_Woh); cudaGetSymbolAddress((void**)&Wol, g_Wol);
    cudaGetSymbolAddress((void**)&kh, g_kh);   cudaGetSymbolAddress((void**)&kl, g_kl);
    cudaGetSymbolAddress((void**)&qh, g_qh);   cudaGetSymbolAddress((void**)&ql, g_ql);
    cudaGetSymbolAddress((void**)&oph, g_oph); cudaGetSymbolAddress((void**)&opl, g_opl);
    cudaGetSymbolAddress((void**)&vp, g_v);
    cudaGetSymbolAddress((void**)&op, g_op);
    cudaGetSymbolAddress((void**)&cm, g_colmax);

    cudaFuncSetAttribute(gemm_mma<2,3>, cudaFuncAttributeMaxDynamicSharedMemorySize, SMEM_SZ);
    cudaFuncSetAttribute(gemm_mma<0,2>, cudaFuncAttributeMaxDynamicSharedMemorySize, SMEM_SZ);
    cudaFuncSetAttribute(gemm_mma<3,3>, cudaFuncAttributeMaxDynamicSharedMemorySize, SMEM_SZ);
    cudaFuncSetAttribute(gemm_mma<4,3>, cudaFuncAttributeMaxDynamicSharedMemorySize, SMEM_SZ);
    cudaFuncSetAttribute(gemm_mma<1,2>, cudaFuncAttributeMaxDynamicSharedMemorySize, SMEM_SZ);

    const float scale = 1.0f / sqrtf((float)CC);

    // 1: init, 2: split_x, 3: splitW  -> launches 4..7 are the big GEMMs (ncu -s 5 target)
    init_kernel<<<2048, 256>>>();
    split_x<<<dim3(TT / 32, CC / 32, BB), dim3(32, 8)>>>(x);
    splitW_all<<<2048, 256>>>(Wq, Wk, Wv, Wout);

    // k = x @ Wk^T -> hilo (3-term)
    gemm_mma<2,3><<<dim3(4, 128, 1), 256, SMEM_SZ>>>(
        xh, xl, Wkh, Wkl, nullptr, nullptr, kh, kl, CC, CC, 0, 0, 0, 0.f, nullptr, 0);
    // v = x @ Wv^T -> plain (2-term)
    gemm_mma<0,2><<<dim3(4, 128, 1), 256, SMEM_SZ>>>(
        xh, xl, Wvh, Wvl, nullptr, vp, nullptr, nullptr, CC, CC, 0, 0, 0, 0.f, nullptr, 0);
    // q[b] = Wq @ xT[b]^T + bq -> hilo (3-term)
    gemm_mma<3,3><<<dim3(4, 8, BB), 256, SMEM_SZ>>>(
        Wqh, Wql, xTh, xTl, bq, nullptr, qh, ql, CC, TT,
        0, (long)CC * TT, (long)NNODE * CC, 0.f, nullptr, 0);
    // sim[b] = scale * k[b] @ q[b]^T, token-major, fused argmax (3-term)
    gemm_mma<4,3><<<dim3(NNODE / 128, TT / 128, BB), 256, SMEM_SZ>>>(
        kh, kl, qh, ql, nullptr, nullptr, nullptr, nullptr, NNODE, CC,
        (long)TT * CC, (long)NNODE * CC, 0, scale, cm, (long)TT);

    cudaMemsetAsync(att, 0, (size_t)BB * NNODE * TT * sizeof(float), 0);
    node_max_kernel<<<(BB * TT) / 256, 256>>>();
    node_sum_kernel<<<(BB * TT) / 256, 256>>>();
    att_scatter_kernel<<<(BB * TT) / 256, 256>>>(att);
    outpre_scatter_kernel<<<BB * TT, 128>>>();

    split2h_v4<<<2048, 256>>>(op, oph, opl, (long)BB * NNODE * CC / 4);
    // out = outpre @ Wout^T + bout (2-term)
    gemm_mma<1,2><<<dim3(4, 64, 1), 256, SMEM_SZ>>>(
        oph, opl, Woh, Wol, bout, out, nullptr, nullptr, CC, CC, 0, 0, 0, 0.f, nullptr, 0);
}

// round 9
// speedup vs baseline: 1.8489x; 1.0122x over previous
#include <cuda_runtime.h>
#include <cuda_fp16.h>
#include <math.h>
#include <stdint.h>

#define BB 8
#define TT 2048
#define CC 512
#define NNODE 1024

// ============================ scratch (static) ============================
#define AL __align__(128)
__device__ AL __half g_xh[BB * TT * CC];
__device__ AL __half g_xl[BB * TT * CC];
__device__ AL __half g_xTh[BB * CC * TT];
__device__ AL __half g_xTl[BB * CC * TT];
__device__ AL __half g_Wqh[NNODE * TT];
__device__ AL __half g_Wql[NNODE * TT];
__device__ AL __half g_Wkh[CC * CC];
__device__ AL __half g_Wkl[CC * CC];
__device__ AL __half g_Wvh[CC * CC];
__device__ AL __half g_Wvl[CC * CC];
__device__ AL __half g_Woh[CC * CC];
__device__ AL __half g_Wol[CC * CC];
__device__ AL __half g_kh[BB * TT * CC];
__device__ AL __half g_kl[BB * TT * CC];
__device__ AL __half g_qh[BB * NNODE * CC];
__device__ AL __half g_ql[BB * NNODE * CC];
__device__ AL __half g_oph[BB * NNODE * CC];
__device__ AL __half g_opl[BB * NNODE * CC];
__device__ AL float g_v[BB * TT * CC];
__device__ AL float g_op[BB * NNODE * CC];
__device__ AL unsigned long long g_colmax[BB * TT];
__device__ AL unsigned int g_Mkey[BB * NNODE];
__device__ AL float g_Z[BB * NNODE];

// ============================ helpers ============================
__device__ __forceinline__ unsigned int fkey(float f) {
    unsigned int u = __float_as_uint(f);
    return (u & 0x80000000u) ? ~u : (u | 0x80000000u);
}
__device__ __forceinline__ float funkey(unsigned int u) {
    unsigned int v = (u & 0x80000000u) ? (u & 0x7fffffffu) : ~u;
    return __uint_as_float(v);
}
__device__ __forceinline__ uint32_t smem_u32(const void* p) {
    uint32_t a;
    asm("{ .reg .u64 t; cvta.to.shared.u64 t, %1; cvt.u32.u64 %0, t; }" : "=r"(a) : "l"(p));
    return a;
}
__device__ __forceinline__ void cp16(uint32_t dst, const void* src) {
    asm volatile("cp.async.cg.shared.global [%0], [%1], 16;" :: "r"(dst), "l"(src) : "memory");
}
__device__ __forceinline__ void cp_commit() {
    asm volatile("cp.async.commit_group;" ::: "memory");
}
template <int N> __device__ __forceinline__ void cp_wait() {
    asm volatile("cp.async.wait_group %0;" :: "n"(N) : "memory");
}
__device__ __forceinline__ void mma16(float* d,
                                      unsigned a0, unsigned a1, unsigned a2, unsigned a3,
                                      unsigned b0, unsigned b1) {
    asm volatile(
        "mma.sync.aligned.m16n8k16.row.col.f32.f16.f16.f32 "
        "{%0,%1,%2,%3},{%4,%5,%6,%7},{%8,%9},{%0,%1,%2,%3};"
        : "+f"(d[0]), "+f"(d[1]), "+f"(d[2]), "+f"(d[3])
        : "r"(a0), "r"(a1), "r"(a2), "r"(a3), "r"(b0), "r"(b1));
}
__device__ __forceinline__ void ldmx4(unsigned& r0, unsigned& r1, unsigned& r2, unsigned& r3,
                                      uint32_t addr) {
    asm volatile("ldmatrix.sync.aligned.m8n8.x4.shared.b16 {%0,%1,%2,%3}, [%4];"
                 : "=r"(r0), "=r"(r1), "=r"(r2), "=r"(r3) : "r"(addr));
}
__device__ __forceinline__ void split_h(float v, __half& h, __half& l) {
    h = __float2half_rn(v);
    l = __float2half_rn(v - __half2float(h));
}
__device__ __forceinline__ unsigned packh2(__half a, __half b) {
    __half2 t = __halves2half2(a, b);
    return *reinterpret_cast<unsigned*>(&t);
}

// ============================ fp16 split mma.sync NT GEMM ============================
// NTERM=3: ah*bh + ah*bl + al*bh.  NTERM=2: ah*bh + al*bh (B-lo dropped, tile not loaded).
// Block 128x128, BK=32 halves, 8 warps 2(m) x 4(n), warp tile 64x32.
// Term-major inner ordering breaks accumulator RAW chains (hh x4nf, hl x4nf, lh x4nf).
// Single __syncthreads per K-iteration (prefetch after sync, depth-1).
// EPI: 0 plain->Cp, 1 plain+colbias->Cp, 2 hilo->Ch/Cl, 3 hilo+rowbias->Ch/Cl, 4 argmax->colmax
static const int SROWB = 80;                        // padded row bytes (32 halves + 16B pad)
static const int TILE_B = 128 * SROWB;              // 10240
static const int STAGE_B = 4 * TILE_B;              // 40960 (Ah, Al, Bh, Bl)
static const int RED_OFF = 2 * STAGE_B;             // 81920
static const int SMEM_SZ = RED_OFF + 1024;          // 82944

template <int EPI, int NTERM>
__global__ __launch_bounds__(256, 2) void gemm_mma(
    const __half* __restrict__ Ahp, const __half* __restrict__ Alp,
    const __half* __restrict__ Bhp, const __half* __restrict__ Blp,
    const float* __restrict__ bias,
    float* __restrict__ Cp, __half* __restrict__ Ch, __half* __restrict__ Cl,
    int Nd, int K,
    long sAz, long sBz, long sCz,
    float scale, unsigned long long* colmax, long sMz)
{
    extern __shared__ __align__(16) char smem[];
    const uint32_t sb = smem_u32(smem);
    const int tid = threadIdx.x;
    const int lane = tid & 31;
    const int wid = tid >> 5;
    const int wm = wid >> 2;
    const int wn = wid & 3;
    const int grp = lane >> 2;
    const int qd = lane & 3;
    const int z = blockIdx.z;
    const long m0 = (long)blockIdx.y * 128;
    const long n0 = (long)blockIdx.x * 128;

    const __half* pT[4] = { Ahp + z * sAz + m0 * K, Alp + z * sAz + m0 * K,
                            Bhp + z * sBz + n0 * K, Blp + z * sBz + n0 * K };
    const __half* src[8];
    uint32_t dst[8];
#pragma unroll
    for (int i = 0; i < 8; i++) {
        int w = i * 256 + tid;
        int tile = w >> 9;
        int row = (w >> 2) & 127;
        int ch = w & 3;
        src[i] = pT[tile] + (long)row * K + ch * 8;
        dst[i] = tile * TILE_B + row * SROWB + ch * 16;
    }

    const int nKB = K >> 5;

    // preload stage 0 only (depth-1 pipeline, single sync per iteration)
#pragma unroll
    for (int i = 0; i < 8; i++)
        if (NTERM == 3 || i < 6) cp16(sb + dst[i], src[i]);
    cp_commit();

    float acc[4][4][4];
#pragma unroll
    for (int mf = 0; mf < 4; mf++)
#pragma unroll
        for (int nf = 0; nf < 4; nf++)
#pragma unroll
            for (int r = 0; r < 4; r++) acc[mf][nf][r] = 0.f;

    const int lrow = lane & 15;
    const int lcol = (lane >> 4) * 8;

    for (int kb = 0; kb < nKB; kb++) {
        cp_wait<0>();          // stage kb complete (this thread)
        __syncthreads();       // all threads' stage-kb copies visible; prior reads of other buf done
        if (kb + 1 < nKB) {
            uint32_t so = ((kb + 1) & 1) * STAGE_B;
            const long ko = (long)(kb + 1) * 32;
#pragma unroll
            for (int i = 0; i < 8; i++)
                if (NTERM == 3 || i < 6) cp16(sb + so + dst[i], src[i] + ko);
            cp_commit();
        }

        const uint32_t stg = sb + (kb & 1) * STAGE_B;
        const uint32_t sAh = stg, sAl = stg + TILE_B;
        const uint32_t sBh = stg + 2 * TILE_B, sBl = stg + 3 * TILE_B;

#pragma unroll
        for (int ks = 0; ks < 2; ks++) {
            const int k0 = ks * 16;
            const uint32_t cofs = (lcol + k0) * 2;
            unsigned rbh[2][4], rbl[2][4];
#pragma unroll
            for (int nfp = 0; nfp < 2; nfp++) {
                uint32_t ro = (uint32_t)(wn * 32 + nfp * 16 + lrow) * SROWB + cofs;
                ldmx4(rbh[nfp][0], rbh[nfp][1], rbh[nfp][2], rbh[nfp][3], sBh + ro);
                if (NTERM == 3)
                    ldmx4(rbl[nfp][0], rbl[nfp][1], rbl[nfp][2], rbl[nfp][3], sBl + ro);
            }
#pragma unroll
            for (int mf = 0; mf < 4; mf++) {
                uint32_t ro = (uint32_t)(wm * 64 + mf * 16 + lrow) * SROWB + cofs;
                unsigned ah0, ah1, ah2, ah3, al0, al1, al2, al3;
                ldmx4(ah0, ah1, ah2, ah3, sAh + ro);
                ldmx4(al0, al1, al2, al3, sAl + ro);
                // pass 1: hh over all 4 nf (independent accumulators)
#pragma unroll
                for (int nfp = 0; nfp < 2; nfp++)
#pragma unroll
                    for (int sub = 0; sub < 2; sub++)
                        mma16(acc[mf][nfp * 2 + sub], ah0, ah1, ah2, ah3,
                              rbh[nfp][sub], rbh[nfp][sub + 2]);
                // pass 2: hl
                if (NTERM == 3) {
#pragma unroll
                    for (int nfp = 0; nfp < 2; nfp++)
#pragma unroll
                        for (int sub = 0; sub < 2; sub++)
                            mma16(acc[mf][nfp * 2 + sub], ah0, ah1, ah2, ah3,
                                  rbl[nfp][sub], rbl[nfp][sub + 2]);
                }
                // pass 3: lh
#pragma unroll
                for (int nfp = 0; nfp < 2; nfp++)
#pragma unroll
                    for (int sub = 0; sub < 2; sub++)
                        mma16(acc[mf][nfp * 2 + sub], al0, al1, al2, al3,
                              rbh[nfp][sub], rbh[nfp][sub + 2]);
            }
        }
    }

    // ---------------- epilogue ----------------
    if constexpr (EPI == 4) {
        unsigned long long* red = (unsigned long long*)(smem + RED_OFF);
        __syncthreads();       // mainloop reads done before red[] reuse (different region; cheap)
        if (tid < 128) red[tid] = 0ull;
        __syncthreads();
#pragma unroll
        for (int mf = 0; mf < 4; mf++) {
#pragma unroll
            for (int half = 0; half < 2; half++) {
                int lr = wm * 64 + mf * 16 + grp + half * 8;
                float bv = -INFINITY; int bc = 0;
#pragma unroll
                for (int nf = 0; nf < 4; nf++) {
#pragma unroll
                    for (int c = 0; c < 2; c++) {
                        float vv = acc[mf][nf][half * 2 + c];
                        int col = (int)n0 + wn * 32 + nf * 8 + qd * 2 + c;
                        if (vv > bv) { bv = vv; bc = col; }
                    }
                }
                unsigned long long pack =
                    ((unsigned long long)fkey(bv * scale) << 32) | (unsigned int)bc;
                unsigned long long o;
                o = __shfl_xor_sync(0xffffffffu, pack, 1); if (o > pack) pack = o;
                o = __shfl_xor_sync(0xffffffffu, pack, 2); if (o > pack) pack = o;
                if (qd == 0) atomicMax(&red[lr], pack);
            }
        }
        __syncthreads();
        if (tid < 128)
            atomicMax(&colmax[z * sMz + m0 + tid], red[tid]);
    } else {
#pragma unroll
        for (int mf = 0; mf < 4; mf++) {
#pragma unroll
            for (int half = 0; half < 2; half++) {
                long row = m0 + wm * 64 + mf * 16 + grp + half * 8;
                float rb = 0.f;
                if constexpr (EPI == 3) rb = bias[row];
                long base = z * sCz + row * (long)Nd + n0 + wn * 32 + qd * 2;
#pragma unroll
                for (int nf = 0; nf < 4; nf++) {
                    float v0 = acc[mf][nf][half * 2 + 0];
                    float v1 = acc[mf][nf][half * 2 + 1];
                    long off = base + nf * 8;
                    if constexpr (EPI == 0 || EPI == 1) {
                        if constexpr (EPI == 1) {
                            v0 += bias[n0 + wn * 32 + nf * 8 + qd * 2 + 0];
                            v1 += bias[n0 + wn * 32 + nf * 8 + qd * 2 + 1];
                        }
                        *reinterpret_cast<float2*>(&Cp[off]) = make_float2(v0, v1);
                    } else {
                        v0 += rb; v1 += rb;
                        __half h0, l0, h1, l1;
                        split_h(v0, h0, l0);
                        split_h(v1, h1, l1);
                        *reinterpret_cast<__half2*>(&Ch[off]) = __halves2half2(h0, h1);
                        *reinterpret_cast<__half2*>(&Cl[off]) = __halves2half2(l0, l1);
                    }
                }
            }
        }
    }
}

// ============================ small kernels ============================
__global__ void init_kernel() {
    int i = blockIdx.x * blockDim.x + threadIdx.x;
    int stride = gridDim.x * blockDim.x;
    for (int j = i; j < BB * TT; j += stride) g_colmax[j] = 0ull;
    for (int j = i; j < BB * NNODE; j += stride) { g_Mkey[j] = 0u; g_Z[j] = 0.f; }
    float4* op4 = reinterpret_cast<float4*>(g_op);
    const int n4 = BB * NNODE * CC / 4;
    for (int j = i; j < n4; j += stride) op4[j] = make_float4(0.f, 0.f, 0.f, 0.f);
}

// fused: x -> (xh, xl) row-major AND (xTh, xTl) transposed, single read of x
__global__ void split_x(const float* __restrict__ x) {
    __shared__ float tile[32][33];
    const int z = blockIdx.z;
    const int t0 = blockIdx.x * 32, c0 = blockIdx.y * 32;
    const int tx = threadIdx.x, ty = threadIdx.y;
#pragma unroll
    for (int i = 0; i < 32; i += 8) {
        long o = ((long)z * TT + t0 + ty + i) * CC + c0 + tx;
        float v = x[o];
        tile[ty + i][tx] = v;
        __half h, l;
        split_h(v, h, l);
        g_xh[o] = h; g_xl[o] = l;
    }
    __syncthreads();
    const int tid = ty * 32 + tx;
    const int cr = tid >> 3;           // 0..31 (c-local)
    const int q = tid & 7;             // 0..7  (t-quad)
    __half hh[4], ll[4];
#pragma unroll
    for (int j = 0; j < 4; j++)
        split_h(tile[4 * q + j][cr], hh[j], ll[j]);
    long ob = ((long)z * CC + c0 + cr) * TT + t0 + 4 * q;
    *reinterpret_cast<uint2*>(&g_xTh[ob]) = make_uint2(packh2(hh[0], hh[1]), packh2(hh[2], hh[3]));
    *reinterpret_cast<uint2*>(&g_xTl[ob]) = make_uint2(packh2(ll[0], ll[1]), packh2(ll[2], ll[3]));
}

__global__ void splitW_all(const float* __restrict__ Wq, const float* __restrict__ Wk,
                           const float* __restrict__ Wv, const float* __restrict__ Wo) {
    const long nq4 = (long)NNODE * TT / 4, nw4 = (long)CC * CC / 4;
    long i = (long)blockIdx.x * blockDim.x + threadIdx.x;
    long stride = (long)gridDim.x * blockDim.x;
    long total = nq4 + 3 * nw4;
    for (long j = i; j < total; j += stride) {
        const float* s; __half *dh, *dl; long o;
        if (j < nq4) { o = j; s = Wq; dh = g_Wqh; dl = g_Wql; }
        else if (j < nq4 + nw4) { o = j - nq4; s = Wk; dh = g_Wkh; dl = g_Wkl; }
        else if (j < nq4 + 2 * nw4) { o = j - nq4 - nw4; s = Wv; dh = g_Wvh; dl = g_Wvl; }
        else { o = j - nq4 - 2 * nw4; s = Wo; dh = g_Woh; dl = g_Wol; }
        float4 v = reinterpret_cast<const float4*>(s)[o];
        __half h0, l0, h1, l1, h2, l2, h3, l3;
        split_h(v.x, h0, l0); split_h(v.y, h1, l1);
        split_h(v.z, h2, l2); split_h(v.w, h3, l3);
        reinterpret_cast<uint2*>(dh)[o] = make_uint2(packh2(h0, h1), packh2(h2, h3));
        reinterpret_cast<uint2*>(dl)[o] = make_uint2(packh2(l0, l1), packh2(l2, l3));
    }
}

__global__ void split2h_v4(const float* __restrict__ in, __half* __restrict__ hp,
                           __half* __restrict__ lp, long n4) {
    long i = (long)blockIdx.x * blockDim.x + threadIdx.x;
    long stride = (long)gridDim.x * blockDim.x;
    for (long j = i; j < n4; j += stride) {
        float4 v = reinterpret_cast<const float4*>(in)[j];
        __half h0, l0, h1, l1, h2, l2, h3, l3;
        split_h(v.x, h0, l0); split_h(v.y, h1, l1);
        split_h(v.z, h2, l2); split_h(v.w, h3, l3);
        reinterpret_cast<uint2*>(hp)[j] = make_uint2(packh2(h0, h1), packh2(h2, h3));
        reinterpret_cast<uint2*>(lp)[j] = make_uint2(packh2(l0, l1), packh2(l2, l3));
    }
}

__global__ void node_max_kernel() {
    int i = blockIdx.x * blockDim.x + threadIdx.x;
    if (i >= BB * TT) return;
    int b = i / TT;
    unsigned long long p = g_colmax[i];
    unsigned int n = (unsigned int)(p & 0xffffffffu);
    atomicMax(&g_Mkey[b * NNODE + n], (unsigned int)(p >> 32));
}

__global__ void node_sum_kernel() {
    int i = blockIdx.x * blockDim.x + threadIdx.x;
    if (i >= BB * TT) return;
    int b = i / TT;
    unsigned long long p = g_colmax[i];
    unsigned int n = (unsigned int)(p & 0xffffffffu);
    int bn = b * NNODE + n;
    float m = funkey((unsigned int)(p >> 32));
    atomicAdd(&g_Z[bn], expf(m - funkey(g_Mkey[bn])));
}

__global__ void att_scatter_kernel(float* __restrict__ att) {
    int i = blockIdx.x * blockDim.x + threadIdx.x;
    if (i >= BB * TT) return;
    int b = i / TT;
    int t = i % TT;
    unsigned long long p = g_colmax[i];
    unsigned int n = (unsigned int)(p & 0xffffffffu);
    int bn = b * NNODE + n;
    float m = funkey((unsigned int)(p >> 32));
    float w = expf(m - funkey(g_Mkey[bn])) / g_Z[bn];
    att[(long)bn * TT + t] = w;
}

__global__ void outpre_scatter_kernel() {
    int i = blockIdx.x;
    int b = i / TT;
    unsigned long long p = g_colmax[i];
    unsigned int n = (unsigned int)(p & 0xffffffffu);
    int bn = b * NNODE + n;
    float m = funkey((unsigned int)(p >> 32));
    float w = expf(m - funkey(g_Mkey[bn])) / g_Z[bn];
    const float4* vrow = reinterpret_cast<const float4*>(g_v + (long)i * CC);
    float* orow = g_op + (long)bn * CC;
    for (int c4 = threadIdx.x; c4 < CC / 4; c4 += blockDim.x) {
        float4 v4 = vrow[c4];
        atomicAdd(&orow[c4 * 4 + 0], w * v4.x);
        atomicAdd(&orow[c4 * 4 + 1], w * v4.y);
        atomicAdd(&orow[c4 * 4 + 2], w * v4.z);
        atomicAdd(&orow[c4 * 4 + 3], w * v4.w);
    }
}

// ============================ launch ============================
extern "C" void kernel_launch(void* const* d_in, const int* in_sizes, int n_in,
                              void* d_out, int out_size)
{
    const float* x    = (const float*)d_in[0];
    const float* Wq   = (const float*)d_in[1];
    const float* bq   = (const float*)d_in[2];
    const float* Wk   = (const float*)d_in[3];
    const float* Wv   = (const float*)d_in[4];
    const float* Wout = (const float*)d_in[5];
    const float* bout = (const float*)d_in[6];

    float* out = (float*)d_out;
    float* att = out + (long)BB * NNODE * CC;

    __half *xh, *xl, *xTh, *xTl, *Wqh, *Wql, *Wkh, *Wkl, *Wvh, *Wvl, *Woh, *Wol;
    __half *kh, *kl, *qh, *ql, *oph, *opl;
    float *vp, *op;
    unsigned long long* cm;
    cudaGetSymbolAddress((void**)&xh, g_xh);   cudaGetSymbolAddress((void**)&xl, g_xl);
    cudaGetSymbolAddress((void**)&xTh, g_xTh); cudaGetSymbolAddress((void**)&xTl, g_xTl);
    cudaGetSymbolAddress((void**)&Wqh, g_Wqh); cudaGetSymbolAddress((void**)&Wql, g_Wql);
    cudaGetSymbolAddress((void**)&Wkh, g_Wkh); cudaGetSymbolAddress((void**)&Wkl, g_Wkl);
    cudaGetSymbolAddress((void**)&Wvh, g_Wvh); cudaGetSymbolAddress((void**)&Wvl, g_Wvl);
    cudaGetSymbolAddress((void**)&Woh, g_Woh); cudaGetSymbolAddress((void**)&Wol, g_Wol);
    cudaGetSymbolAddress((void**)&kh, g_kh);   cudaGetSymbolAddress((void**)&kl, g_kl);
    cudaGetSymbolAddress((void**)&qh, g_qh);   cudaGetSymbolAddress((void**)&ql, g_ql);
    cudaGetSymbolAddress((void**)&oph, g_oph); cudaGetSymbolAddress((void**)&opl, g_opl);
    cudaGetSymbolAddress((void**)&vp, g_v);
    cudaGetSymbolAddress((void**)&op, g_op);
    cudaGetSymbolAddress((void**)&cm, g_colmax);

    cudaFuncSetAttribute(gemm_mma<2,3>, cudaFuncAttributeMaxDynamicSharedMemorySize, SMEM_SZ);
    cudaFuncSetAttribute(gemm_mma<0,2>, cudaFuncAttributeMaxDynamicSharedMemorySize, SMEM_SZ);
    cudaFuncSetAttribute(gemm_mma<3,3>, cudaFuncAttributeMaxDynamicSharedMemorySize, SMEM_SZ);
    cudaFuncSetAttribute(gemm_mma<4,3>, cudaFuncAttributeMaxDynamicSharedMemorySize, SMEM_SZ);
    cudaFuncSetAttribute(gemm_mma<1,2>, cudaFuncAttributeMaxDynamicSharedMemorySize, SMEM_SZ);

    const float scale = 1.0f / sqrtf((float)CC);

    // 1: init, 2: split_x, 3: splitW  -> launches 4..7 are the big GEMMs (ncu -s 5 target)
    init_kernel<<<2048, 256>>>();
    split_x<<<dim3(TT / 32, CC / 32, BB), dim3(32, 8)>>>(x);
    splitW_all<<<2048, 256>>>(Wq, Wk, Wv, Wout);

    // k = x @ Wk^T -> hilo (3-term)
    gemm_mma<2,3><<<dim3(4, 128, 1), 256, SMEM_SZ>>>(
        xh, xl, Wkh, Wkl, nullptr, nullptr, kh, kl, CC, CC, 0, 0, 0, 0.f, nullptr, 0);
    // v = x @ Wv^T -> plain (2-term)
    gemm_mma<0,2><<<dim3(4, 128, 1), 256, SMEM_SZ>>>(
        xh, xl, Wvh, Wvl, nullptr, vp, nullptr, nullptr, CC, CC, 0, 0, 0, 0.f, nullptr, 0);
    // q[b] = Wq @ xT[b]^T + bq -> hilo (3-term)
    gemm_mma<3,3><<<dim3(4, 8, BB), 256, SMEM_SZ>>>(
        Wqh, Wql, xTh, xTl, bq, nullptr, qh, ql, CC, TT,
        0, (long)CC * TT, (long)NNODE * CC, 0.f, nullptr, 0);
    // sim[b] = scale * k[b] @ q[b]^T, token-major, fused argmax (3-term)
    gemm_mma<4,3><<<dim3(NNODE / 128, TT / 128, BB), 256, SMEM_SZ>>>(
        kh, kl, qh, ql, nullptr, nullptr, nullptr, nullptr, NNODE, CC,
        (long)TT * CC, (long)NNODE * CC, 0, scale, cm, (long)TT);

    cudaMemsetAsync(att, 0, (size_t)BB * NNODE * TT * sizeof(float), 0);
    node_max_kernel<<<(BB * TT) / 256, 256>>>();
    node_sum_kernel<<<(BB * TT) / 256, 256>>>();
    att_scatter_kernel<<<(BB * TT) / 256, 256>>>(att);
    outpre_scatter_kernel<<<BB * TT, 128>>>();

    split2h_v4<<<2048, 256>>>(op, oph, opl, (long)BB * NNODE * CC / 4);
    // out = outpre @ Wout^T + bout (2-term)
    gemm_mma<1,2><<<dim3(4, 64, 1), 256, SMEM_SZ>>>(
        oph, opl, Woh, Wol, bout, out, nullptr, nullptr, CC, CC, 0, 0, 0, 0.f, nullptr, 0);
}

// round 11
// speedup vs baseline: 1.9254x; 1.0414x over previous
#include <cuda_runtime.h>
#include <cuda_fp16.h>
#include <math.h>
#include <stdint.h>

#define BB 8
#define TT 2048
#define CC 512
#define NNODE 1024

// ============================ scratch (static) ============================
#define AL __align__(128)
__device__ AL __half g_xh[BB * TT * CC];
__device__ AL __half g_xl[BB * TT * CC];
__device__ AL __half g_xTh[BB * CC * TT];
__device__ AL __half g_xTl[BB * CC * TT];
__device__ AL __half g_Wqh[NNODE * TT];
__device__ AL __half g_Wql[NNODE * TT];
__device__ AL __half g_Wkh[CC * CC];
__device__ AL __half g_Wkl[CC * CC];
__device__ AL __half g_MTh[CC * CC];     // MT = Wv^T Wout^T, row-major [d', c], hi plane
__device__ AL __half g_MTl[CC * CC];     // lo plane
__device__ AL __half g_kh[BB * TT * CC];
__device__ AL __half g_kl[BB * TT * CC];
__device__ AL __half g_qh[BB * NNODE * CC];
__device__ AL __half g_ql[BB * NNODE * CC];
__device__ AL float g_vw[BB * TT * CC];  // vw = x @ MT^T  (= v @ Wout^T)
__device__ AL unsigned long long g_colmax[BB * TT];
__device__ AL unsigned int g_Mkey[BB * NNODE];
__device__ AL float g_Z[BB * NNODE];

// ============================ helpers ============================
__device__ __forceinline__ unsigned int fkey(float f) {
    unsigned int u = __float_as_uint(f);
    return (u & 0x80000000u) ? ~u : (u | 0x80000000u);
}
__device__ __forceinline__ float funkey(unsigned int u) {
    unsigned int v = (u & 0x80000000u) ? (u & 0x7fffffffu) : ~u;
    return __uint_as_float(v);
}
__device__ __forceinline__ uint32_t smem_u32(const void* p) {
    uint32_t a;
    asm("{ .reg .u64 t; cvta.to.shared.u64 t, %1; cvt.u32.u64 %0, t; }" : "=r"(a) : "l"(p));
    return a;
}
__device__ __forceinline__ void cp16(uint32_t dst, const void* src) {
    asm volatile("cp.async.cg.shared.global [%0], [%1], 16;" :: "r"(dst), "l"(src) : "memory");
}
__device__ __forceinline__ void cp_commit() {
    asm volatile("cp.async.commit_group;" ::: "memory");
}
template <int N> __device__ __forceinline__ void cp_wait() {
    asm volatile("cp.async.wait_group %0;" :: "n"(N) : "memory");
}
__device__ __forceinline__ void mma16(float* d,
                                      unsigned a0, unsigned a1, unsigned a2, unsigned a3,
                                      unsigned b0, unsigned b1) {
    asm volatile(
        "mma.sync.aligned.m16n8k16.row.col.f32.f16.f16.f32 "
        "{%0,%1,%2,%3},{%4,%5,%6,%7},{%8,%9},{%0,%1,%2,%3};"
        : "+f"(d[0]), "+f"(d[1]), "+f"(d[2]), "+f"(d[3])
        : "r"(a0), "r"(a1), "r"(a2), "r"(a3), "r"(b0), "r"(b1));
}
__device__ __forceinline__ void ldmx4(unsigned& r0, unsigned& r1, unsigned& r2, unsigned& r3,
                                      uint32_t addr) {
    asm volatile("ldmatrix.sync.aligned.m8n8.x4.shared.b16 {%0,%1,%2,%3}, [%4];"
                 : "=r"(r0), "=r"(r1), "=r"(r2), "=r"(r3) : "r"(addr));
}
__device__ __forceinline__ void split_h(float v, __half& h, __half& l) {
    h = __float2half_rn(v);
    l = __float2half_rn(v - __half2float(h));
}
__device__ __forceinline__ unsigned packh2(__half a, __half b) {
    __half2 t = __halves2half2(a, b);
    return *reinterpret_cast<unsigned*>(&t);
}

// ============================ fp16 split mma.sync NT GEMM ============================
// NTERM=3: ah*bh + ah*bl + al*bh.  NTERM=2: ah*bh + al*bh (B-lo dropped, tile not loaded).
// Block 128x128, BK=32 halves, 8 warps 2(m) x 4(n), warp tile 64x32.
// EPI: 0 plain->Cp, 2 hilo->Ch/Cl, 3 hilo+rowbias->Ch/Cl, 4 argmax->colmax
static const int SROWB = 80;
static const int TILE_B = 128 * SROWB;              // 10240
static const int STAGE_B = 4 * TILE_B;              // 40960
static const int RED_OFF = 2 * STAGE_B;             // 81920
static const int SMEM_SZ = RED_OFF + 1024;          // 82944

template <int EPI, int NTERM>
__global__ __launch_bounds__(256, 2) void gemm_mma(
    const __half* __restrict__ Ahp, const __half* __restrict__ Alp,
    const __half* __restrict__ Bhp, const __half* __restrict__ Blp,
    const float* __restrict__ bias,
    float* __restrict__ Cp, __half* __restrict__ Ch, __half* __restrict__ Cl,
    int Nd, int K,
    long sAz, long sBz, long sCz,
    float scale, unsigned long long* colmax, long sMz)
{
    extern __shared__ __align__(16) char smem[];
    const uint32_t sb = smem_u32(smem);
    const int tid = threadIdx.x;
    const int lane = tid & 31;
    const int wid = tid >> 5;
    const int wm = wid >> 2;
    const int wn = wid & 3;
    const int grp = lane >> 2;
    const int qd = lane & 3;
    const int z = blockIdx.z;
    const long m0 = (long)blockIdx.y * 128;
    const long n0 = (long)blockIdx.x * 128;

    const __half* pT[4] = { Ahp + z * sAz + m0 * K, Alp + z * sAz + m0 * K,
                            Bhp + z * sBz + n0 * K, Blp + z * sBz + n0 * K };
    const __half* src[8];
    uint32_t dst[8];
#pragma unroll
    for (int i = 0; i < 8; i++) {
        int w = i * 256 + tid;
        int tile = w >> 9;
        int row = (w >> 2) & 127;
        int ch = w & 3;
        src[i] = pT[tile] + (long)row * K + ch * 8;
        dst[i] = tile * TILE_B + row * SROWB + ch * 16;
    }

    const int nKB = K >> 5;

#pragma unroll
    for (int i = 0; i < 8; i++)
        if (NTERM == 3 || i < 6) cp16(sb + dst[i], src[i]);
    cp_commit();

    float acc[4][4][4];
#pragma unroll
    for (int mf = 0; mf < 4; mf++)
#pragma unroll
        for (int nf = 0; nf < 4; nf++)
#pragma unroll
            for (int r = 0; r < 4; r++) acc[mf][nf][r] = 0.f;

    const int lrow = lane & 15;
    const int lcol = (lane >> 4) * 8;

    for (int kb = 0; kb < nKB; kb++) {
        cp_wait<0>();
        __syncthreads();
        if (kb + 1 < nKB) {
            uint32_t so = ((kb + 1) & 1) * STAGE_B;
            const long ko = (long)(kb + 1) * 32;
#pragma unroll
            for (int i = 0; i < 8; i++)
                if (NTERM == 3 || i < 6) cp16(sb + so + dst[i], src[i] + ko);
            cp_commit();
        }

        const uint32_t stg = sb + (kb & 1) * STAGE_B;
        const uint32_t sAh = stg, sAl = stg + TILE_B;
        const uint32_t sBh = stg + 2 * TILE_B, sBl = stg + 3 * TILE_B;

#pragma unroll
        for (int ks = 0; ks < 2; ks++) {
            const int k0 = ks * 16;
            const uint32_t cofs = (lcol + k0) * 2;
            unsigned rbh[2][4], rbl[2][4];
#pragma unroll
            for (int nfp = 0; nfp < 2; nfp++) {
                uint32_t ro = (uint32_t)(wn * 32 + nfp * 16 + lrow) * SROWB + cofs;
                ldmx4(rbh[nfp][0], rbh[nfp][1], rbh[nfp][2], rbh[nfp][3], sBh + ro);
                if (NTERM == 3)
                    ldmx4(rbl[nfp][0], rbl[nfp][1], rbl[nfp][2], rbl[nfp][3], sBl + ro);
            }
#pragma unroll
            for (int mf = 0; mf < 4; mf++) {
                uint32_t ro = (uint32_t)(wm * 64 + mf * 16 + lrow) * SROWB + cofs;
                unsigned ah0, ah1, ah2, ah3, al0, al1, al2, al3;
                ldmx4(ah0, ah1, ah2, ah3, sAh + ro);
                ldmx4(al0, al1, al2, al3, sAl + ro);
#pragma unroll
                for (int nfp = 0; nfp < 2; nfp++)
#pragma unroll
                    for (int sub = 0; sub < 2; sub++)
                        mma16(acc[mf][nfp * 2 + sub], ah0, ah1, ah2, ah3,
                              rbh[nfp][sub], rbh[nfp][sub + 2]);
                if (NTERM == 3) {
#pragma unroll
                    for (int nfp = 0; nfp < 2; nfp++)
#pragma unroll
                        for (int sub = 0; sub < 2; sub++)
                            mma16(acc[mf][nfp * 2 + sub], ah0, ah1, ah2, ah3,
                                  rbl[nfp][sub], rbl[nfp][sub + 2]);
                }
#pragma unroll
                for (int nfp = 0; nfp < 2; nfp++)
#pragma unroll
                    for (int sub = 0; sub < 2; sub++)
                        mma16(acc[mf][nfp * 2 + sub], al0, al1, al2, al3,
                              rbh[nfp][sub], rbh[nfp][sub + 2]);
            }
        }
    }

    // ---------------- epilogue ----------------
    if constexpr (EPI == 4) {
        unsigned long long* red = (unsigned long long*)(smem + RED_OFF);
        __syncthreads();
        if (tid < 128) red[tid] = 0ull;
        __syncthreads();
#pragma unroll
        for (int mf = 0; mf < 4; mf++) {
#pragma unroll
            for (int half = 0; half < 2; half++) {
                int lr = wm * 64 + mf * 16 + grp + half * 8;
                float bv = -INFINITY; int bc = 0;
#pragma unroll
                for (int nf = 0; nf < 4; nf++) {
#pragma unroll
                    for (int c = 0; c < 2; c++) {
                        float vv = acc[mf][nf][half * 2 + c];
                        int col = (int)n0 + wn * 32 + nf * 8 + qd * 2 + c;
                        if (vv > bv) { bv = vv; bc = col; }
                    }
                }
                unsigned long long pack =
                    ((unsigned long long)fkey(bv * scale) << 32) | (unsigned int)bc;
                unsigned long long o;
                o = __shfl_xor_sync(0xffffffffu, pack, 1); if (o > pack) pack = o;
                o = __shfl_xor_sync(0xffffffffu, pack, 2); if (o > pack) pack = o;
                if (qd == 0) atomicMax(&red[lr], pack);
            }
        }
        __syncthreads();
        if (tid < 128)
            atomicMax(&colmax[z * sMz + m0 + tid], red[tid]);
    } else {
#pragma unroll
        for (int mf = 0; mf < 4; mf++) {
#pragma unroll
            for (int half = 0; half < 2; half++) {
                long row = m0 + wm * 64 + mf * 16 + grp + half * 8;
                float rb = 0.f;
                if constexpr (EPI == 3) rb = bias[row];
                long base = z * sCz + row * (long)Nd + n0 + wn * 32 + qd * 2;
#pragma unroll
                for (int nf = 0; nf < 4; nf++) {
                    float v0 = acc[mf][nf][half * 2 + 0];
                    float v1 = acc[mf][nf][half * 2 + 1];
                    long off = base + nf * 8;
                    if constexpr (EPI == 0) {
                        *reinterpret_cast<float2*>(&Cp[off]) = make_float2(v0, v1);
                    } else {
                        v0 += rb; v1 += rb;
                        __half h0, l0, h1, l1;
                        split_h(v0, h0, l0);
                        split_h(v1, h1, l1);
                        *reinterpret_cast<__half2*>(&Ch[off]) = __halves2half2(h0, h1);
                        *reinterpret_cast<__half2*>(&Cl[off]) = __halves2half2(l0, l1);
                    }
                }
            }
        }
    }
}

// ============================ small kernels ============================
// init: colmax/Mkey/Z zero, out[b,n,:] = bout (bias pre-init for direct scatter)
__global__ void init_kernel(float* __restrict__ out, const float* __restrict__ bout) {
    int i = blockIdx.x * blockDim.x + threadIdx.x;
    int stride = gridDim.x * blockDim.x;
    for (int j = i; j < BB * TT; j += stride) g_colmax[j] = 0ull;
    for (int j = i; j < BB * NNODE; j += stride) { g_Mkey[j] = 0u; g_Z[j] = 0.f; }
    const int n4 = BB * NNODE * CC / 4;
    const float4* b4 = reinterpret_cast<const float4*>(bout);
    float4* o4 = reinterpret_cast<float4*>(out);
    for (int j = i; j < n4; j += stride) o4[j] = b4[j & (CC / 4 - 1)];
}

// fused: x -> (xh, xl) row-major AND (xTh, xTl) transposed, single read of x
__global__ void split_x(const float* __restrict__ x) {
    __shared__ float tile[32][33];
    const int z = blockIdx.z;
    const int t0 = blockIdx.x * 32, c0 = blockIdx.y * 32;
    const int tx = threadIdx.x, ty = threadIdx.y;
#pragma unroll
    for (int i = 0; i < 32; i += 8) {
        long o = ((long)z * TT + t0 + ty + i) * CC + c0 + tx;
        float v = x[o];
        tile[ty + i][tx] = v;
        __half h, l;
        split_h(v, h, l);
        g_xh[o] = h; g_xl[o] = l;
    }
    __syncthreads();
    const int tid = ty * 32 + tx;
    const int cr = tid >> 3;
    const int q = tid & 7;
    __half hh[4], ll[4];
#pragma unroll
    for (int j = 0; j < 4; j++)
        split_h(tile[4 * q + j][cr], hh[j], ll[j]);
    long ob = ((long)z * CC + c0 + cr) * TT + t0 + 4 * q;
    *reinterpret_cast<uint2*>(&g_xTh[ob]) = make_uint2(packh2(hh[0], hh[1]), packh2(hh[2], hh[3]));
    *reinterpret_cast<uint2*>(&g_xTl[ob]) = make_uint2(packh2(ll[0], ll[1]), packh2(ll[2], ll[3]));
}

// split Wq + Wk only (Wv/Wout consumed in fp32 by compute_MT)
__global__ void splitW_qk(const float* __restrict__ Wq, const float* __restrict__ Wk) {
    const long nq4 = (long)NNODE * TT / 4, nw4 = (long)CC * CC / 4;
    long i = (long)blockIdx.x * blockDim.x + threadIdx.x;
    long stride = (long)gridDim.x * blockDim.x;
    long total = nq4 + nw4;
    for (long j = i; j < total; j += stride) {
        const float* s; __half *dh, *dl; long o;
        if (j < nq4) { o = j; s = Wq; dh = g_Wqh; dl = g_Wql; }
        else { o = j - nq4; s = Wk; dh = g_Wkh; dl = g_Wkl; }
        float4 v = reinterpret_cast<const float4*>(s)[o];
        __half h0, l0, h1, l1, h2, l2, h3, l3;
        split_h(v.x, h0, l0); split_h(v.y, h1, l1);
        split_h(v.z, h2, l2); split_h(v.w, h3, l3);
        reinterpret_cast<uint2*>(dh)[o] = make_uint2(packh2(h0, h1), packh2(h2, h3));
        reinterpret_cast<uint2*>(dl)[o] = make_uint2(packh2(l0, l1), packh2(l2, l3));
    }
}

// MT[d'][c] = sum_c' Wout[d'][c'] * Wv[c'][c]   (fp32, then hi/lo split to g_MTh/g_MTl)
// Grid (16,16), block (32,8); each thread computes 4 rows x 1 col of a 32x32 tile.
__global__ void compute_MT(const float* __restrict__ Wv, const float* __restrict__ Wout) {
    __shared__ float As[32][33], Bs[32][33];
    const int bx = blockIdx.x, by = blockIdx.y;
    const int tx = threadIdx.x, ty = threadIdx.y;
    float acc[4] = {0.f, 0.f, 0.f, 0.f};
    for (int kt = 0; kt < CC / 32; kt++) {
#pragma unroll
        for (int i = 0; i < 32; i += 8) {
            As[ty + i][tx] = Wout[(long)(by * 32 + ty + i) * CC + kt * 32 + tx];
            Bs[ty + i][tx] = Wv[(long)(kt * 32 + ty + i) * CC + bx * 32 + tx];
        }
        __syncthreads();
#pragma unroll
        for (int k = 0; k < 32; k++) {
            float b = Bs[k][tx];
#pragma unroll
            for (int r = 0; r < 4; r++)
                acc[r] += As[ty * 4 + r][k] * b;
        }
        __syncthreads();
    }
#pragma unroll
    for (int r = 0; r < 4; r++) {
        long o = (long)(by * 32 + ty * 4 + r) * CC + bx * 32 + tx;
        __half h, l;
        split_h(acc[r], h, l);
        g_MTh[o] = h; g_MTl[o] = l;
    }
}

__global__ void node_max_kernel() {
    int i = blockIdx.x * blockDim.x + threadIdx.x;
    if (i >= BB * TT) return;
    int b = i / TT;
    unsigned long long p = g_colmax[i];
    unsigned int n = (unsigned int)(p & 0xffffffffu);
    atomicMax(&g_Mkey[b * NNODE + n], (unsigned int)(p >> 32));
}

__global__ void node_sum_kernel() {
    int i = blockIdx.x * blockDim.x + threadIdx.x;
    if (i >= BB * TT) return;
    int b = i / TT;
    unsigned long long p = g_colmax[i];
    unsigned int n = (unsigned int)(p & 0xffffffffu);
    int bn = b * NNODE + n;
    float m = funkey((unsigned int)(p >> 32));
    atomicAdd(&g_Z[bn], expf(m - funkey(g_Mkey[bn])));
}

// fused: write att[bn][t] = w AND out[bn][:] += w * vw[b,t,:]  (out pre-initialized to bout)
__global__ void scatter_kernel(float* __restrict__ att, float* __restrict__ out) {
    int i = blockIdx.x;            // one block per (b, t)
    int b = i / TT;
    int t = i % TT;
    unsigned long long p = g_colmax[i];
    unsigned int n = (unsigned int)(p & 0xffffffffu);
    int bn = b * NNODE + n;
    float m = funkey((unsigned int)(p >> 32));
    float w = expf(m - funkey(g_Mkey[bn])) / g_Z[bn];
    if (threadIdx.x == 0) att[(long)bn * TT + t] = w;
    const float4* vrow = reinterpret_cast<const float4*>(g_vw + (long)i * CC);
    float* orow = out + (long)bn * CC;
    for (int c4 = threadIdx.x; c4 < CC / 4; c4 += blockDim.x) {
        float4 v4 = vrow[c4];
        atomicAdd(&orow[c4 * 4 + 0], w * v4.x);
        atomicAdd(&orow[c4 * 4 + 1], w * v4.y);
        atomicAdd(&orow[c4 * 4 + 2], w * v4.z);
        atomicAdd(&orow[c4 * 4 + 3], w * v4.w);
    }
}

// ============================ launch ============================
extern "C" void kernel_launch(void* const* d_in, const int* in_sizes, int n_in,
                              void* d_out, int out_size)
{
    const float* x    = (const float*)d_in[0];
    const float* Wq   = (const float*)d_in[1];
    const float* bq   = (const float*)d_in[2];
    const float* Wk   = (const float*)d_in[3];
    const float* Wv   = (const float*)d_in[4];
    const float* Wout = (const float*)d_in[5];
    const float* bout = (const float*)d_in[6];

    float* out = (float*)d_out;
    float* att = out + (long)BB * NNODE * CC;

    __half *xh, *xl, *xTh, *xTl, *Wqh, *Wql, *Wkh, *Wkl, *MTh, *MTl;
    __half *kh, *kl, *qh, *ql;
    float *vwp;
    unsigned long long* cm;
    cudaGetSymbolAddress((void**)&xh, g_xh);   cudaGetSymbolAddress((void**)&xl, g_xl);
    cudaGetSymbolAddress((void**)&xTh, g_xTh); cudaGetSymbolAddress((void**)&xTl, g_xTl);
    cudaGetSymbolAddress((void**)&Wqh, g_Wqh); cudaGetSymbolAddress((void**)&Wql, g_Wql);
    cudaGetSymbolAddress((void**)&Wkh, g_Wkh); cudaGetSymbolAddress((void**)&Wkl, g_Wkl);
    cudaGetSymbolAddress((void**)&MTh, g_MTh); cudaGetSymbolAddress((void**)&MTl, g_MTl);
    cudaGetSymbolAddress((void**)&kh, g_kh);   cudaGetSymbolAddress((void**)&kl, g_kl);
    cudaGetSymbolAddress((void**)&qh, g_qh);   cudaGetSymbolAddress((void**)&ql, g_ql);
    cudaGetSymbolAddress((void**)&vwp, g_vw);
    cudaGetSymbolAddress((void**)&cm, g_colmax);

    cudaFuncSetAttribute(gemm_mma<2,3>, cudaFuncAttributeMaxDynamicSharedMemorySize, SMEM_SZ);
    cudaFuncSetAttribute(gemm_mma<0,2>, cudaFuncAttributeMaxDynamicSharedMemorySize, SMEM_SZ);
    cudaFuncSetAttribute(gemm_mma<3,3>, cudaFuncAttributeMaxDynamicSharedMemorySize, SMEM_SZ);
    cudaFuncSetAttribute(gemm_mma<4,3>, cudaFuncAttributeMaxDynamicSharedMemorySize, SMEM_SZ);

    const float scale = 1.0f / sqrtf((float)CC);

    init_kernel<<<2048, 256>>>(out, bout);
    split_x<<<dim3(TT / 32, CC / 32, BB), dim3(32, 8)>>>(x);
    splitW_qk<<<2048, 256>>>(Wq, Wk);
    compute_MT<<<dim3(CC / 32, CC / 32), dim3(32, 8)>>>(Wv, Wout);

    // k = x @ Wk^T -> hilo (3-term)
    gemm_mma<2,3><<<dim3(4, 128, 1), 256, SMEM_SZ>>>(
        xh, xl, Wkh, Wkl, nullptr, nullptr, kh, kl, CC, CC, 0, 0, 0, 0.f, nullptr, 0);
    // vw = x @ MT^T -> plain fp32 (2-term; MT-lo dropped)
    gemm_mma<0,2><<<dim3(4, 128, 1), 256, SMEM_SZ>>>(
        xh, xl, MTh, MTl, nullptr, vwp, nullptr, nullptr, CC, CC, 0, 0, 0, 0.f, nullptr, 0);
    // q[b] = Wq @ xT[b]^T + bq -> hilo (3-term)
    gemm_mma<3,3><<<dim3(4, 8, BB), 256, SMEM_SZ>>>(
        Wqh, Wql, xTh, xTl, bq, nullptr, qh, ql, CC, TT,
        0, (long)CC * TT, (long)NNODE * CC, 0.f, nullptr, 0);
    // sim[b] = scale * k[b] @ q[b]^T, token-major, fused argmax (3-term)
    gemm_mma<4,3><<<dim3(NNODE / 128, TT / 128, BB), 256, SMEM_SZ>>>(
        kh, kl, qh, ql, nullptr, nullptr, nullptr, nullptr, NNODE, CC,
        (long)TT * CC, (long)NNODE * CC, 0, scale, cm, (long)TT);

    cudaMemsetAsync(att, 0, (size_t)BB * NNODE * TT * sizeof(float), 0);
    node_max_kernel<<<(BB * TT) / 256, 256>>>();
    node_sum_kernel<<<(BB * TT) / 256, 256>>>();
    scatter_kernel<<<BB * TT, 128>>>(att, out);
}

// round 13
// speedup vs baseline: 2.0806x; 1.0806x over previous
#include <cuda_runtime.h>
#include <cuda_fp16.h>
#include <math.h>
#include <stdint.h>

#define BB 8
#define TT 2048
#define CC 512
#define NNODE 1024

// ============================ scratch (static) ============================
#define AL __align__(128)
__device__ AL __half g_xh[BB * TT * CC];
__device__ AL __half g_xl[BB * TT * CC];
__device__ AL __half g_xTh[BB * CC * TT];
__device__ AL __half g_xTl[BB * CC * TT];
__device__ AL __half g_Wqh[NNODE * TT];
__device__ AL __half g_Wql[NNODE * TT];
__device__ AL __half g_WkTh[CC * CC];    // Wk transposed [c, d], hi/lo
__device__ AL __half g_WkTl[CC * CC];
__device__ AL __half g_MTh[CC * CC];     // MT = Wout @ Wv  (row d', col c), hi/lo
__device__ AL __half g_MTl[CC * CC];
__device__ AL __half g_sh[BB * NNODE * CC];  // qWk[n,c] hilo
__device__ AL __half g_sl[BB * NNODE * CC];
__device__ AL __half g_qh[BB * NNODE * CC];
__device__ AL __half g_ql[BB * NNODE * CC];
__device__ AL float g_vw[BB * TT * CC];  // vw = x @ MT^T  (= v @ Wout^T)
__device__ AL unsigned long long g_colmax[BB * TT];
__device__ AL unsigned int g_Mkey[BB * NNODE];
__device__ AL float g_Z[BB * NNODE];

// ============================ helpers ============================
__device__ __forceinline__ unsigned int fkey(float f) {
    unsigned int u = __float_as_uint(f);
    return (u & 0x80000000u) ? ~u : (u | 0x80000000u);
}
__device__ __forceinline__ float funkey(unsigned int u) {
    unsigned int v = (u & 0x80000000u) ? (u & 0x7fffffffu) : ~u;
    return __uint_as_float(v);
}
__device__ __forceinline__ uint32_t smem_u32(const void* p) {
    uint32_t a;
    asm("{ .reg .u64 t; cvta.to.shared.u64 t, %1; cvt.u32.u64 %0, t; }" : "=r"(a) : "l"(p));
    return a;
}
__device__ __forceinline__ void cp16(uint32_t dst, const void* src) {
    asm volatile("cp.async.cg.shared.global [%0], [%1], 16;" :: "r"(dst), "l"(src) : "memory");
}
__device__ __forceinline__ void cp_commit() {
    asm volatile("cp.async.commit_group;" ::: "memory");
}
template <int N> __device__ __forceinline__ void cp_wait() {
    asm volatile("cp.async.wait_group %0;" :: "n"(N) : "memory");
}
__device__ __forceinline__ void mma16(float* d,
                                      unsigned a0, unsigned a1, unsigned a2, unsigned a3,
                                      unsigned b0, unsigned b1) {
    asm volatile(
        "mma.sync.aligned.m16n8k16.row.col.f32.f16.f16.f32 "
        "{%0,%1,%2,%3},{%4,%5,%6,%7},{%8,%9},{%0,%1,%2,%3};"
        : "+f"(d[0]), "+f"(d[1]), "+f"(d[2]), "+f"(d[3])
        : "r"(a0), "r"(a1), "r"(a2), "r"(a3), "r"(b0), "r"(b1));
}
__device__ __forceinline__ void ldmx4(unsigned& r0, unsigned& r1, unsigned& r2, unsigned& r3,
                                      uint32_t addr) {
    asm volatile("ldmatrix.sync.aligned.m8n8.x4.shared.b16 {%0,%1,%2,%3}, [%4];"
                 : "=r"(r0), "=r"(r1), "=r"(r2), "=r"(r3) : "r"(addr));
}
__device__ __forceinline__ void split_h(float v, __half& h, __half& l) {
    h = __float2half_rn(v);
    l = __float2half_rn(v - __half2float(h));
}
__device__ __forceinline__ unsigned packh2(__half a, __half b) {
    __half2 t = __halves2half2(a, b);
    return *reinterpret_cast<unsigned*>(&t);
}

// ============================ fp16 split mma.sync NT GEMM ============================
// NTERM=3: ah*bh + ah*bl + al*bh.  NTERM=2: ah*bh + al*bh (B-lo dropped, tile not loaded).
// Block 128x128, BK=32 halves, 8 warps 2(m) x 4(n), warp tile 64x32.
// EPI: 0 plain->Cp, 2 hilo->Ch/Cl, 3 hilo+rowbias->Ch/Cl, 4 argmax->colmax
static const int SROWB = 80;
static const int TILE_B = 128 * SROWB;              // 10240
static const int STAGE_B = 4 * TILE_B;              // 40960
static const int RED_OFF = 2 * STAGE_B;             // 81920
static const int SMEM_SZ = RED_OFF + 1024;          // 82944

template <int EPI, int NTERM>
__global__ __launch_bounds__(256, 2) void gemm_mma(
    const __half* __restrict__ Ahp, const __half* __restrict__ Alp,
    const __half* __restrict__ Bhp, const __half* __restrict__ Blp,
    const float* __restrict__ bias,
    float* __restrict__ Cp, __half* __restrict__ Ch, __half* __restrict__ Cl,
    int Nd, int K,
    long sAz, long sBz, long sCz,
    float scale, unsigned long long* colmax, long sMz)
{
    extern __shared__ __align__(16) char smem[];
    const uint32_t sb = smem_u32(smem);
    const int tid = threadIdx.x;
    const int lane = tid & 31;
    const int wid = tid >> 5;
    const int wm = wid >> 2;
    const int wn = wid & 3;
    const int grp = lane >> 2;
    const int qd = lane & 3;
    const int z = blockIdx.z;
    const long m0 = (long)blockIdx.y * 128;
    const long n0 = (long)blockIdx.x * 128;

    const __half* pT[4] = { Ahp + z * sAz + m0 * K, Alp + z * sAz + m0 * K,
                            Bhp + z * sBz + n0 * K, Blp + z * sBz + n0 * K };
    const __half* src[8];
    uint32_t dst[8];
#pragma unroll
    for (int i = 0; i < 8; i++) {
        int w = i * 256 + tid;
        int tile = w >> 9;
        int row = (w >> 2) & 127;
        int ch = w & 3;
        src[i] = pT[tile] + (long)row * K + ch * 8;
        dst[i] = tile * TILE_B + row * SROWB + ch * 16;
    }

    const int nKB = K >> 5;

#pragma unroll
    for (int i = 0; i < 8; i++)
        if (NTERM == 3 || i < 6) cp16(sb + dst[i], src[i]);
    cp_commit();

    float acc[4][4][4];
#pragma unroll
    for (int mf = 0; mf < 4; mf++)
#pragma unroll
        for (int nf = 0; nf < 4; nf++)
#pragma unroll
            for (int r = 0; r < 4; r++) acc[mf][nf][r] = 0.f;

    const int lrow = lane & 15;
    const int lcol = (lane >> 4) * 8;

    for (int kb = 0; kb < nKB; kb++) {
        cp_wait<0>();
        __syncthreads();
        if (kb + 1 < nKB) {
            uint32_t so = ((kb + 1) & 1) * STAGE_B;
            const long ko = (long)(kb + 1) * 32;
#pragma unroll
            for (int i = 0; i < 8; i++)
                if (NTERM == 3 || i < 6) cp16(sb + so + dst[i], src[i] + ko);
            cp_commit();
        }

        const uint32_t stg = sb + (kb & 1) * STAGE_B;
        const uint32_t sAh = stg, sAl = stg + TILE_B;
        const uint32_t sBh = stg + 2 * TILE_B, sBl = stg + 3 * TILE_B;

#pragma unroll
        for (int ks = 0; ks < 2; ks++) {
            const int k0 = ks * 16;
            const uint32_t cofs = (lcol + k0) * 2;
            unsigned rbh[2][4], rbl[2][4];
#pragma unroll
            for (int nfp = 0; nfp < 2; nfp++) {
                uint32_t ro = (uint32_t)(wn * 32 + nfp * 16 + lrow) * SROWB + cofs;
                ldmx4(rbh[nfp][0], rbh[nfp][1], rbh[nfp][2], rbh[nfp][3], sBh + ro);
                if (NTERM == 3)
                    ldmx4(rbl[nfp][0], rbl[nfp][1], rbl[nfp][2], rbl[nfp][3], sBl + ro);
            }
#pragma unroll
            for (int mf = 0; mf < 4; mf++) {
                uint32_t ro = (uint32_t)(wm * 64 + mf * 16 + lrow) * SROWB + cofs;
                unsigned ah0, ah1, ah2, ah3, al0, al1, al2, al3;
                ldmx4(ah0, ah1, ah2, ah3, sAh + ro);
                ldmx4(al0, al1, al2, al3, sAl + ro);
#pragma unroll
                for (int nfp = 0; nfp < 2; nfp++)
#pragma unroll
                    for (int sub = 0; sub < 2; sub++)
                        mma16(acc[mf][nfp * 2 + sub], ah0, ah1, ah2, ah3,
                              rbh[nfp][sub], rbh[nfp][sub + 2]);
                if (NTERM == 3) {
#pragma unroll
                    for (int nfp = 0; nfp < 2; nfp++)
#pragma unroll
                        for (int sub = 0; sub < 2; sub++)
                            mma16(acc[mf][nfp * 2 + sub], ah0, ah1, ah2, ah3,
                                  rbl[nfp][sub], rbl[nfp][sub + 2]);
                }
#pragma unroll
                for (int nfp = 0; nfp < 2; nfp++)
#pragma unroll
                    for (int sub = 0; sub < 2; sub++)
                        mma16(acc[mf][nfp * 2 + sub], al0, al1, al2, al3,
                              rbh[nfp][sub], rbh[nfp][sub + 2]);
            }
        }
    }

    // ---------------- epilogue ----------------
    if constexpr (EPI == 4) {
        unsigned long long* red = (unsigned long long*)(smem + RED_OFF);
        __syncthreads();
        if (tid < 128) red[tid] = 0ull;
        __syncthreads();
#pragma unroll
        for (int mf = 0; mf < 4; mf++) {
#pragma unroll
            for (int half = 0; half < 2; half++) {
                int lr = wm * 64 + mf * 16 + grp + half * 8;
                float bv = -INFINITY; int bc = 0;
#pragma unroll
                for (int nf = 0; nf < 4; nf++) {
#pragma unroll
                    for (int c = 0; c < 2; c++) {
                        float vv = acc[mf][nf][half * 2 + c];
                        int col = (int)n0 + wn * 32 + nf * 8 + qd * 2 + c;
                        if (vv > bv) { bv = vv; bc = col; }
                    }
                }
                unsigned long long pack =
                    ((unsigned long long)fkey(bv * scale) << 32) | (unsigned int)bc;
                unsigned long long o;
                o = __shfl_xor_sync(0xffffffffu, pack, 1); if (o > pack) pack = o;
                o = __shfl_xor_sync(0xffffffffu, pack, 2); if (o > pack) pack = o;
                if (qd == 0) atomicMax(&red[lr], pack);
            }
        }
        __syncthreads();
        if (tid < 128)
            atomicMax(&colmax[z * sMz + m0 + tid], red[tid]);
    } else {
#pragma unroll
        for (int mf = 0; mf < 4; mf++) {
#pragma unroll
            for (int half = 0; half < 2; half++) {
                long row = m0 + wm * 64 + mf * 16 + grp + half * 8;
                float rb = 0.f;
                if constexpr (EPI == 3) rb = bias[row];
                long base = z * sCz + row * (long)Nd + n0 + wn * 32 + qd * 2;
#pragma unroll
                for (int nf = 0; nf < 4; nf++) {
                    float v0 = acc[mf][nf][half * 2 + 0];
                    float v1 = acc[mf][nf][half * 2 + 1];
                    long off = base + nf * 8;
                    if constexpr (EPI == 0) {
                        *reinterpret_cast<float2*>(&Cp[off]) = make_float2(v0, v1);
                    } else {
                        v0 += rb; v1 += rb;
                        __half h0, l0, h1, l1;
                        split_h(v0, h0, l0);
                        split_h(v1, h1, l1);
                        *reinterpret_cast<__half2*>(&Ch[off]) = __halves2half2(h0, h1);
                        *reinterpret_cast<__half2*>(&Cl[off]) = __halves2half2(l0, l1);
                    }
                }
            }
        }
    }
}

// ============================ small kernels ============================
// init: colmax/Mkey/Z zero, out[b,n,:] = bout (bias pre-init for direct scatter)
__global__ void init_kernel(float* __restrict__ out, const float* __restrict__ bout) {
    int i = blockIdx.x * blockDim.x + threadIdx.x;
    int stride = gridDim.x * blockDim.x;
    for (int j = i; j < BB * TT; j += stride) g_colmax[j] = 0ull;
    for (int j = i; j < BB * NNODE; j += stride) { g_Mkey[j] = 0u; g_Z[j] = 0.f; }
    const int n4 = BB * NNODE * CC / 4;
    const float4* b4 = reinterpret_cast<const float4*>(bout);
    float4* o4 = reinterpret_cast<float4*>(out);
    for (int j = i; j < n4; j += stride) o4[j] = b4[j & (CC / 4 - 1)];
}

// fused: x -> (xh, xl) row-major AND (xTh, xTl) transposed, single read of x
__global__ void split_x(const float* __restrict__ x) {
    __shared__ float tile[32][33];
    const int z = blockIdx.z;
    const int t0 = blockIdx.x * 32, c0 = blockIdx.y * 32;
    const int tx = threadIdx.x, ty = threadIdx.y;
#pragma unroll
    for (int i = 0; i < 32; i += 8) {
        long o = ((long)z * TT + t0 + ty + i) * CC + c0 + tx;
        float v = x[o];
        tile[ty + i][tx] = v;
        __half h, l;
        split_h(v, h, l);
        g_xh[o] = h; g_xl[o] = l;
    }
    __syncthreads();
    const int tid = ty * 32 + tx;
    const int cr = tid >> 3;
    const int q = tid & 7;
    __half hh[4], ll[4];
#pragma unroll
    for (int j = 0; j < 4; j++)
        split_h(tile[4 * q + j][cr], hh[j], ll[j]);
    long ob = ((long)z * CC + c0 + cr) * TT + t0 + 4 * q;
    *reinterpret_cast<uint2*>(&g_xTh[ob]) = make_uint2(packh2(hh[0], hh[1]), packh2(hh[2], hh[3]));
    *reinterpret_cast<uint2*>(&g_xTl[ob]) = make_uint2(packh2(ll[0], ll[1]), packh2(ll[2], ll[3]));
}

// split Wq (row-major)
__global__ void splitWq(const float* __restrict__ Wq) {
    const long nq4 = (long)NNODE * TT / 4;
    long i = (long)blockIdx.x * blockDim.x + threadIdx.x;
    long stride = (long)gridDim.x * blockDim.x;
    for (long j = i; j < nq4; j += stride) {
        float4 v = reinterpret_cast<const float4*>(Wq)[j];
        __half h0, l0, h1, l1, h2, l2, h3, l3;
        split_h(v.x, h0, l0); split_h(v.y, h1, l1);
        split_h(v.z, h2, l2); split_h(v.w, h3, l3);
        reinterpret_cast<uint2*>(g_Wqh)[j] = make_uint2(packh2(h0, h1), packh2(h2, h3));
        reinterpret_cast<uint2*>(g_Wql)[j] = make_uint2(packh2(l0, l1), packh2(l2, l3));
    }
}

// transpose-split Wk: WkT[c][d] = Wk[d][c], hilo planes
__global__ void splitWkT(const float* __restrict__ Wk) {
    __shared__ float tile[32][33];
    const int d0 = blockIdx.x * 32, c0 = blockIdx.y * 32;
    const int tx = threadIdx.x, ty = threadIdx.y;
#pragma unroll
    for (int i = 0; i < 32; i += 8)
        tile[ty + i][tx] = Wk[(long)(d0 + ty + i) * CC + c0 + tx];
    __syncthreads();
    const int tid = ty * 32 + tx;
    const int cr = tid >> 3;           // 0..31 (c-local)
    const int q = tid & 7;             // 0..7  (d-quad)
    __half hh[4], ll[4];
#pragma unroll
    for (int j = 0; j < 4; j++)
        split_h(tile[4 * q + j][cr], hh[j], ll[j]);
    long ob = (long)(c0 + cr) * CC + d0 + 4 * q;
    *reinterpret_cast<uint2*>(&g_WkTh[ob]) = make_uint2(packh2(hh[0], hh[1]), packh2(hh[2], hh[3]));
    *reinterpret_cast<uint2*>(&g_WkTl[ob]) = make_uint2(packh2(ll[0], ll[1]), packh2(ll[2], ll[3]));
}

// MT[d'][c] = sum_c' Wout[d'][c'] * Wv[c'][c]   (fp32, then hilo split)
__global__ void compute_MT(const float* __restrict__ Wv, const float* __restrict__ Wout) {
    __shared__ float As[32][33], Bs[32][33];
    const int bx = blockIdx.x, by = blockIdx.y;
    const int tx = threadIdx.x, ty = threadIdx.y;
    float acc[4] = {0.f, 0.f, 0.f, 0.f};
    for (int kt = 0; kt < CC / 32; kt++) {
#pragma unroll
        for (int i = 0; i < 32; i += 8) {
            As[ty + i][tx] = Wout[(long)(by * 32 + ty + i) * CC + kt * 32 + tx];
            Bs[ty + i][tx] = Wv[(long)(kt * 32 + ty + i) * CC + bx * 32 + tx];
        }
        __syncthreads();
#pragma unroll
        for (int k = 0; k < 32; k++) {
            float b = Bs[k][tx];
#pragma unroll
            for (int r = 0; r < 4; r++)
                acc[r] += As[ty * 4 + r][k] * b;
        }
        __syncthreads();
    }
#pragma unroll
    for (int r = 0; r < 4; r++) {
        long o = (long)(by * 32 + ty * 4 + r) * CC + bx * 32 + tx;
        __half h, l;
        split_h(acc[r], h, l);
        g_MTh[o] = h; g_MTl[o] = l;
    }
}

__global__ void node_max_kernel() {
    int i = blockIdx.x * blockDim.x + threadIdx.x;
    if (i >= BB * TT) return;
    int b = i / TT;
    unsigned long long p = g_colmax[i];
    unsigned int n = (unsigned int)(p & 0xffffffffu);
    atomicMax(&g_Mkey[b * NNODE + n], (unsigned int)(p >> 32));
}

__global__ void node_sum_kernel() {
    int i = blockIdx.x * blockDim.x + threadIdx.x;
    if (i >= BB * TT) return;
    int b = i / TT;
    unsigned long long p = g_colmax[i];
    unsigned int n = (unsigned int)(p & 0xffffffffu);
    int bn = b * NNODE + n;
    float m = funkey((unsigned int)(p >> 32));
    atomicAdd(&g_Z[bn], expf(m - funkey(g_Mkey[bn])));
}

// fused: att[bn][t] = w AND out[bn][:] += w * vw[b,t,:]  (out pre-initialized to bout)
__global__ void scatter_kernel(float* __restrict__ att, float* __restrict__ out) {
    int i = blockIdx.x;            // one block per (b, t)
    int b = i / TT;
    int t = i % TT;
    unsigned long long p = g_colmax[i];
    unsigned int n = (unsigned int)(p & 0xffffffffu);
    int bn = b * NNODE + n;
    float m = funkey((unsigned int)(p >> 32));
    float w = expf(m - funkey(g_Mkey[bn])) / g_Z[bn];
    if (threadIdx.x == 0) att[(long)bn * TT + t] = w;
    const float4* vrow = reinterpret_cast<const float4*>(g_vw + (long)i * CC);
    float* orow = out + (long)bn * CC;
    for (int c4 = threadIdx.x; c4 < CC / 4; c4 += blockDim.x) {
        float4 v4 = vrow[c4];
        atomicAdd(&orow[c4 * 4 + 0], w * v4.x);
        atomicAdd(&orow[c4 * 4 + 1], w * v4.y);
        atomicAdd(&orow[c4 * 4 + 2], w * v4.z);
        atomicAdd(&orow[c4 * 4 + 3], w * v4.w);
    }
}

// ============================ launch ============================
extern "C" void kernel_launch(void* const* d_in, const int* in_sizes, int n_in,
                              void* d_out, int out_size)
{
    const float* x    = (const float*)d_in[0];
    const float* Wq   = (const float*)d_in[1];
    const float* bq   = (const float*)d_in[2];
    const float* Wk   = (const float*)d_in[3];
    const float* Wv   = (const float*)d_in[4];
    const float* Wout = (const float*)d_in[5];
    const float* bout = (const float*)d_in[6];

    float* out = (float*)d_out;
    float* att = out + (long)BB * NNODE * CC;

    __half *xh, *xl, *xTh, *xTl, *Wqh, *Wql, *WkTh, *WkTl, *MTh, *MTl;
    __half *sh, *sl, *qh, *ql;
    float *vwp;
    unsigned long long* cm;
    cudaGetSymbolAddress((void**)&xh, g_xh);     cudaGetSymbolAddress((void**)&xl, g_xl);
    cudaGetSymbolAddress((void**)&xTh, g_xTh);   cudaGetSymbolAddress((void**)&xTl, g_xTl);
    cudaGetSymbolAddress((void**)&Wqh, g_Wqh);   cudaGetSymbolAddress((void**)&Wql, g_Wql);
    cudaGetSymbolAddress((void**)&WkTh, g_WkTh); cudaGetSymbolAddress((void**)&WkTl, g_WkTl);
    cudaGetSymbolAddress((void**)&MTh, g_MTh);   cudaGetSymbolAddress((void**)&MTl, g_MTl);
    cudaGetSymbolAddress((void**)&sh, g_sh);     cudaGetSymbolAddress((void**)&sl, g_sl);
    cudaGetSymbolAddress((void**)&qh, g_qh);     cudaGetSymbolAddress((void**)&ql, g_ql);
    cudaGetSymbolAddress((void**)&vwp, g_vw);
    cudaGetSymbolAddress((void**)&cm, g_colmax);

    cudaFuncSetAttribute(gemm_mma<2,3>, cudaFuncAttributeMaxDynamicSharedMemorySize, SMEM_SZ);
    cudaFuncSetAttribute(gemm_mma<0,2>, cudaFuncAttributeMaxDynamicSharedMemorySize, SMEM_SZ);
    cudaFuncSetAttribute(gemm_mma<3,3>, cudaFuncAttributeMaxDynamicSharedMemorySize, SMEM_SZ);
    cudaFuncSetAttribute(gemm_mma<4,3>, cudaFuncAttributeMaxDynamicSharedMemorySize, SMEM_SZ);

    const float scale = 1.0f / sqrtf((float)CC);

    init_kernel<<<2048, 256>>>(out, bout);
    split_x<<<dim3(TT / 32, CC / 32, BB), dim3(32, 8)>>>(x);
    splitWq<<<2048, 256>>>(Wq);
    splitWkT<<<dim3(CC / 32, CC / 32), dim3(32, 8)>>>(Wk);
    compute_MT<<<dim3(CC / 32, CC / 32), dim3(32, 8)>>>(Wv, Wout);

    // q[b] = Wq @ xT[b]^T + bq -> hilo (3-term)
    gemm_mma<3,3><<<dim3(4, 8, BB), 256, SMEM_SZ>>>(
        Wqh, Wql, xTh, xTl, bq, nullptr, qh, ql, CC, TT,
        0, (long)CC * TT, (long)NNODE * CC, 0.f, nullptr, 0);
    // qWk[b][n,c] = q[b] @ WkT^T -> hilo (3-term)   (M=1024, N=512, K=512)
    gemm_mma<2,3><<<dim3(4, 8, BB), 256, SMEM_SZ>>>(
        qh, ql, WkTh, WkTl, nullptr, nullptr, sh, sl, CC, CC,
        (long)NNODE * CC, 0, (long)NNODE * CC, 0.f, nullptr, 0);
    // vw = x @ MT^T -> plain fp32 (2-term)
    gemm_mma<0,2><<<dim3(4, 128, 1), 256, SMEM_SZ>>>(
        xh, xl, MTh, MTl, nullptr, vwp, nullptr, nullptr, CC, CC, 0, 0, 0, 0.f, nullptr, 0);
    // sim[b] = scale * x[b] @ qWk[b]^T, token-major, fused argmax (3-term)
    gemm_mma<4,3><<<dim3(NNODE / 128, TT / 128, BB), 256, SMEM_SZ>>>(
        xh, xl, sh, sl, nullptr, nullptr, nullptr, nullptr, NNODE, CC,
        (long)TT * CC, (long)NNODE * CC, 0, scale, cm, (long)TT);

    cudaMemsetAsync(att, 0, (size_t)BB * NNODE * TT * sizeof(float), 0);
    node_max_kernel<<<(BB * TT) / 256, 256>>>();
    node_sum_kernel<<<(BB * TT) / 256, 256>>>();
    scatter_kernel<<<BB * TT, 128>>>(att, out);
}